// round 1
// baseline (speedup 1.0000x reference)
#include <cuda_runtime.h>
#include <math.h>

#define S_LEN 2048
#define DIM   1024
#define NH    16
#define DHEAD 64
#define BATCH 2
#define M_ROWS (BATCH * S_LEN)   // 4096

// Scratch (no dynamic allocation allowed): Q/K/V in head-split layout
// [B*H, S, DH], plus concat-head attention output [M_ROWS, DIM].
__device__ float g_Q[BATCH * NH * S_LEN * DHEAD];
__device__ float g_K[BATCH * NH * S_LEN * DHEAD];
__device__ float g_V[BATCH * NH * S_LEN * DHEAD];
__device__ float g_AO[M_ROWS * DIM];

// ---------------------------------------------------------------------------
// GEMM: out[m,n] = sum_k A[m,k] * W[n,k] + bias[n]
// A: [M_ROWS, DIM] row-major, W: [DIM, DIM] row-major (so W.T is applied).
// SPLIT=true scatters output into head-split layout [B*H, S, DH].
// 128x128 block tile, BK=8, 256 threads, 8x8 per thread.
// ---------------------------------------------------------------------------
template <bool SPLIT>
__global__ void __launch_bounds__(256)
gemm_nt(const float* __restrict__ A, const float* __restrict__ W,
        const float* __restrict__ bias, float* __restrict__ out)
{
    __shared__ float As[8][128];
    __shared__ float Bs[8][128];

    const int bm = blockIdx.y * 128;
    const int bn = blockIdx.x * 128;
    const int tid = threadIdx.x;

    const int ldrow = tid >> 1;          // 0..127
    const int ldcol = (tid & 1) * 4;     // 0 or 4
    const int ty = tid >> 4;             // 0..15  (rows)
    const int tx = tid & 15;             // 0..15  (cols)

    const float* Ap = A + (size_t)(bm + ldrow) * DIM + ldcol;
    const float* Wp = W + (size_t)(bn + ldrow) * DIM + ldcol;

    float acc[8][8];
#pragma unroll
    for (int i = 0; i < 8; i++)
#pragma unroll
        for (int j = 0; j < 8; j++) acc[i][j] = 0.0f;

    for (int kt = 0; kt < DIM; kt += 8) {
        float4 a4 = *(const float4*)(Ap + kt);
        float4 b4 = *(const float4*)(Wp + kt);
        As[ldcol + 0][ldrow] = a4.x;
        As[ldcol + 1][ldrow] = a4.y;
        As[ldcol + 2][ldrow] = a4.z;
        As[ldcol + 3][ldrow] = a4.w;
        Bs[ldcol + 0][ldrow] = b4.x;
        Bs[ldcol + 1][ldrow] = b4.y;
        Bs[ldcol + 2][ldrow] = b4.z;
        Bs[ldcol + 3][ldrow] = b4.w;
        __syncthreads();

#pragma unroll
        for (int k = 0; k < 8; k++) {
            float a[8], b[8];
            float4 t;
            t = *(const float4*)&As[k][ty * 8 + 0]; a[0]=t.x; a[1]=t.y; a[2]=t.z; a[3]=t.w;
            t = *(const float4*)&As[k][ty * 8 + 4]; a[4]=t.x; a[5]=t.y; a[6]=t.z; a[7]=t.w;
            t = *(const float4*)&Bs[k][tx * 8 + 0]; b[0]=t.x; b[1]=t.y; b[2]=t.z; b[3]=t.w;
            t = *(const float4*)&Bs[k][tx * 8 + 4]; b[4]=t.x; b[5]=t.y; b[6]=t.z; b[7]=t.w;
#pragma unroll
            for (int i = 0; i < 8; i++)
#pragma unroll
                for (int j = 0; j < 8; j++)
                    acc[i][j] = fmaf(a[i], b[j], acc[i][j]);
        }
        __syncthreads();
    }

    // Epilogue: bias + store
#pragma unroll
    for (int i = 0; i < 8; i++) {
        const int m = bm + ty * 8 + i;
#pragma unroll
        for (int j = 0; j < 8; j++) {
            const int n = bn + tx * 8 + j;
            const float val = acc[i][j] + bias[n];
            if (SPLIT) {
                const int b = m / S_LEN;
                const int s = m % S_LEN;
                const int h = n / DHEAD;
                const int dh = n % DHEAD;
                out[(((size_t)(b * NH + h)) * S_LEN + s) * DHEAD + dh] = val;
            } else {
                out[(size_t)m * DIM + n] = val;
            }
        }
    }
}

// ---------------------------------------------------------------------------
// Flash attention (fp32, causal). One block per (q-tile of 64, head n).
// 256 threads as 16x16; each thread owns a 4x4 score tile and 4x4 O tile.
// SMEM: Q [64][68], K->P (reused) [64][68], V [64][68]  = 52224 B (dynamic).
// ---------------------------------------------------------------------------
#define FPAD 68

__global__ void __launch_bounds__(256) flash_attn()
{
    extern __shared__ float sm[];
    float* Qs  = sm;                 // 64*FPAD
    float* KPs = sm + 64 * FPAD;     // K tile, later reused as P
    float* Vs  = sm + 2 * 64 * FPAD;

    const int qt = blockIdx.x;       // 0..31
    const int n  = blockIdx.y;       // 0..31 (b*NH + h)
    const int tid = threadIdx.x;
    const int ty = tid >> 4;         // 0..15 -> rows ty*4..ty*4+3
    const int tx = tid & 15;         // 0..15 -> cols tx*4..tx*4+3

    const int lrow = tid >> 2;            // 0..63
    const int lcol = (tid & 3) * 16;      // 0,16,32,48

    const float* Qg = g_Q + ((size_t)n * S_LEN + qt * 64) * DHEAD;
    const float* Kg = g_K + (size_t)n * S_LEN * DHEAD;
    const float* Vg = g_V + (size_t)n * S_LEN * DHEAD;

    // Load Q tile, folding in softmax scale 1/sqrt(64) = 0.125
    const float scale = 0.125f;
#pragma unroll
    for (int i = 0; i < 4; i++) {
        float4 v = *(const float4*)(Qg + lrow * DHEAD + lcol + i * 4);
        float* d = Qs + lrow * FPAD + lcol + i * 4;
        d[0] = v.x * scale; d[1] = v.y * scale; d[2] = v.z * scale; d[3] = v.w * scale;
    }

    float m_old[4], l[4], o[4][4];
#pragma unroll
    for (int i = 0; i < 4; i++) {
        m_old[i] = -3.0e38f;
        l[i] = 0.0f;
#pragma unroll
        for (int j = 0; j < 4; j++) o[i][j] = 0.0f;
    }

    for (int kt = 0; kt <= qt; kt++) {
        __syncthreads();  // covers Q-load (iter 0) and previous P/V reads

        // Load K and V tiles
        const float* Kt = Kg + (size_t)(kt * 64) * DHEAD;
        const float* Vt = Vg + (size_t)(kt * 64) * DHEAD;
#pragma unroll
        for (int i = 0; i < 4; i++) {
            float4 kv = *(const float4*)(Kt + lrow * DHEAD + lcol + i * 4);
            *(float4*)(KPs + lrow * FPAD + lcol + i * 4) = kv;
            float4 vv = *(const float4*)(Vt + lrow * DHEAD + lcol + i * 4);
            *(float4*)(Vs + lrow * FPAD + lcol + i * 4) = vv;
        }
        __syncthreads();

        // S = Q * K^T   (4x4 per thread)
        float s[4][4];
#pragma unroll
        for (int i = 0; i < 4; i++)
#pragma unroll
            for (int j = 0; j < 4; j++) s[i][j] = 0.0f;

#pragma unroll 4
        for (int dd = 0; dd < DHEAD; dd += 4) {
            float4 q4[4], k4[4];
#pragma unroll
            for (int ri = 0; ri < 4; ri++)
                q4[ri] = *(const float4*)(Qs + (ty * 4 + ri) * FPAD + dd);
#pragma unroll
            for (int ci = 0; ci < 4; ci++)
                k4[ci] = *(const float4*)(KPs + (tx * 4 + ci) * FPAD + dd);
#pragma unroll
            for (int ri = 0; ri < 4; ri++) {
                const float* qf = (const float*)&q4[ri];
#pragma unroll
                for (int ci = 0; ci < 4; ci++) {
                    const float* kf = (const float*)&k4[ci];
                    s[ri][ci] = fmaf(qf[0], kf[0], s[ri][ci]);
                    s[ri][ci] = fmaf(qf[1], kf[1], s[ri][ci]);
                    s[ri][ci] = fmaf(qf[2], kf[2], s[ri][ci]);
                    s[ri][ci] = fmaf(qf[3], kf[3], s[ri][ci]);
                }
            }
        }

        // Causal mask on the diagonal tile
        if (kt == qt) {
#pragma unroll
            for (int ri = 0; ri < 4; ri++)
#pragma unroll
                for (int ci = 0; ci < 4; ci++)
                    if (tx * 4 + ci > ty * 4 + ri) s[ri][ci] = -3.0e38f;
        }

        // Online softmax per row (reduce across the 16 tx lanes)
#pragma unroll
        for (int ri = 0; ri < 4; ri++) {
            float mx = fmaxf(fmaxf(s[ri][0], s[ri][1]), fmaxf(s[ri][2], s[ri][3]));
#pragma unroll
            for (int off = 8; off >= 1; off >>= 1)
                mx = fmaxf(mx, __shfl_xor_sync(0xffffffffu, mx, off));
            const float m_new = fmaxf(m_old[ri], mx);
            const float alpha = __expf(m_old[ri] - m_new);
            float sum = 0.0f;
#pragma unroll
            for (int ci = 0; ci < 4; ci++) {
                const float p = __expf(s[ri][ci] - m_new);
                s[ri][ci] = p;
                sum += p;
            }
#pragma unroll
            for (int off = 8; off >= 1; off >>= 1)
                sum += __shfl_xor_sync(0xffffffffu, sum, off);
            l[ri] = l[ri] * alpha + sum;
            m_old[ri] = m_new;
#pragma unroll
            for (int j = 0; j < 4; j++) o[ri][j] *= alpha;
        }

        __syncthreads();  // done reading K tile; safe to overwrite with P

        // Stage P into SMEM (reuse K tile region)
#pragma unroll
        for (int ri = 0; ri < 4; ri++)
#pragma unroll
            for (int ci = 0; ci < 4; ci++)
                KPs[(ty * 4 + ri) * FPAD + tx * 4 + ci] = s[ri][ci];
        __syncthreads();

        // O += P * V   (4x4 per thread; cols here are head dims)
#pragma unroll 4
        for (int cc = 0; cc < 64; cc += 4) {
            float4 p4[4], v4[4];
#pragma unroll
            for (int ri = 0; ri < 4; ri++)
                p4[ri] = *(const float4*)(KPs + (ty * 4 + ri) * FPAD + cc);
#pragma unroll
            for (int cj = 0; cj < 4; cj++)
                v4[cj] = *(const float4*)(Vs + (cc + cj) * FPAD + tx * 4);
#pragma unroll
            for (int ri = 0; ri < 4; ri++) {
                const float* pf = (const float*)&p4[ri];
#pragma unroll
                for (int cj = 0; cj < 4; cj++) {
                    const float* vf = (const float*)&v4[cj];
                    o[ri][0] = fmaf(pf[cj], vf[0], o[ri][0]);
                    o[ri][1] = fmaf(pf[cj], vf[1], o[ri][1]);
                    o[ri][2] = fmaf(pf[cj], vf[2], o[ri][2]);
                    o[ri][3] = fmaf(pf[cj], vf[3], o[ri][3]);
                }
            }
        }
    }

    // Epilogue: normalize and store into concat-head layout [M_ROWS, DIM]
    const int b = n >> 4;
    const int h = n & 15;
#pragma unroll
    for (int ri = 0; ri < 4; ri++) {
        const float inv = 1.0f / l[ri];
        const int row_g = b * S_LEN + qt * 64 + ty * 4 + ri;
        const int col_g = h * DHEAD + tx * 4;
        float4 ov = make_float4(o[ri][0] * inv, o[ri][1] * inv,
                                o[ri][2] * inv, o[ri][3] * inv);
        *(float4*)(g_AO + (size_t)row_g * DIM + col_g) = ov;
    }
}

// ---------------------------------------------------------------------------
// kernel_launch
// Inputs (metadata order): x, mask, Wq, bq, Wk, bk, Wv, bv, Wo, bo
// mask is always tril in this problem; causality is hardcoded in flash_attn.
// ---------------------------------------------------------------------------
extern "C" void kernel_launch(void* const* d_in, const int* in_sizes, int n_in,
                              void* d_out, int out_size)
{
    const float* x  = (const float*)d_in[0];
    const float* Wq = (const float*)d_in[2];
    const float* bq = (const float*)d_in[3];
    const float* Wk = (const float*)d_in[4];
    const float* bk = (const float*)d_in[5];
    const float* Wv = (const float*)d_in[6];
    const float* bv = (const float*)d_in[7];
    const float* Wo = (const float*)d_in[8];
    const float* bo = (const float*)d_in[9];
    float* out = (float*)d_out;

    void *pQ, *pK, *pV, *pAO;
    cudaGetSymbolAddress(&pQ, g_Q);
    cudaGetSymbolAddress(&pK, g_K);
    cudaGetSymbolAddress(&pV, g_V);
    cudaGetSymbolAddress(&pAO, g_AO);

    const dim3 ggrid(DIM / 128, M_ROWS / 128);  // (8, 32)
    gemm_nt<true><<<ggrid, 256>>>(x, Wq, bq, (float*)pQ);
    gemm_nt<true><<<ggrid, 256>>>(x, Wk, bk, (float*)pK);
    gemm_nt<true><<<ggrid, 256>>>(x, Wv, bv, (float*)pV);

    const int smem = 3 * 64 * FPAD * (int)sizeof(float);  // 52224
    cudaFuncSetAttribute(flash_attn, cudaFuncAttributeMaxDynamicSharedMemorySize, smem);
    flash_attn<<<dim3(S_LEN / 64, BATCH * NH), 256, smem>>>();

    gemm_nt<false><<<ggrid, 256>>>((const float*)pAO, Wo, bo, out);
}

// round 2
// speedup vs baseline: 1.2807x; 1.2807x over previous
#include <cuda_runtime.h>
#include <math.h>
#include <stdint.h>

#define S_LEN 2048
#define DIM   1024
#define NH    16
#define DHEAD 64
#define BATCH 2
#define M_ROWS (BATCH * S_LEN)   // 4096

// Scratch (no dynamic allocation allowed): Q/K/V in head-split layout
// [B*H, S, DH], plus concat-head attention output [M_ROWS, DIM].
__device__ float g_Q[BATCH * NH * S_LEN * DHEAD];
__device__ float g_K[BATCH * NH * S_LEN * DHEAD];
__device__ float g_V[BATCH * NH * S_LEN * DHEAD];
__device__ float g_AO[M_ROWS * DIM];

// ---------------------------------------------------------------------------
// Helpers: cp.async, tf32 conversion, mma
// ---------------------------------------------------------------------------
__device__ __forceinline__ uint32_t cvta_smem(const void* p) {
    return (uint32_t)__cvta_generic_to_shared(p);
}
__device__ __forceinline__ void cp_async16(uint32_t dst, const void* src) {
    asm volatile("cp.async.cg.shared.global [%0], [%1], 16;" :: "r"(dst), "l"(src));
}
__device__ __forceinline__ void cp_commit() {
    asm volatile("cp.async.commit_group;");
}
__device__ __forceinline__ uint32_t f2tf32(float x) {
    uint32_t r;
    asm("cvt.rna.tf32.f32 %0, %1;" : "=r"(r) : "f"(x));
    return r;
}
// split x into hi (tf32) + lo (tf32 of residual)
__device__ __forceinline__ void tf32_split(float x, uint32_t& hi, uint32_t& lo) {
    hi = f2tf32(x);
    lo = f2tf32(x - __uint_as_float(hi));
}

#define MMA_TF32(c, a, b)                                                     \
    asm volatile(                                                             \
        "mma.sync.aligned.m16n8k8.row.col.f32.tf32.tf32.f32 "                 \
        "{%0,%1,%2,%3}, {%4,%5,%6,%7}, {%8,%9}, {%0,%1,%2,%3};"               \
        : "+f"((c)[0]), "+f"((c)[1]), "+f"((c)[2]), "+f"((c)[3])              \
        : "r"((a)[0]), "r"((a)[1]), "r"((a)[2]), "r"((a)[3]),                 \
          "r"((b)[0]), "r"((b)[1]))

// ---------------------------------------------------------------------------
// TF32 tensor-core GEMM with 3xTF32 precision compensation.
// out[m,n] = sum_k A[m,k]*W[n,k] + bias[n]
// BM=BN=128, BK=16, 256 threads (8 warps as 4Mx2N, warp tile 32x64).
// Double-buffered cp.async staging. SPLIT=true scatters into head-split.
// ---------------------------------------------------------------------------
#define BM 128
#define BN 128
#define BK 16
#define GPAD 20   // floats per smem row (16B-aligned, conflict-free frag loads)

template <bool SPLIT>
__global__ void __launch_bounds__(256)
gemm_tf32(const float* __restrict__ A, const float* __restrict__ W,
          const float* __restrict__ bias, float* __restrict__ out)
{
    __shared__ float As[2][BM * GPAD];
    __shared__ float Bs[2][BN * GPAD];

    const int tid  = threadIdx.x;
    const int lane = tid & 31;
    const int wid  = tid >> 5;
    const int bm = blockIdx.y * BM;
    const int bn = blockIdx.x * BN;
    const int wm = (wid >> 1) * 32;   // 0,32,64,96
    const int wn = (wid & 1) * 64;    // 0,64

    // staging: each thread copies one float4 from 2 rows of A and of W
    const int lrow = tid >> 2;            // 0..63
    const int lk   = (tid & 3) * 4;       // 0,4,8,12
    const float* Ag = A + (size_t)(bm + lrow) * DIM + lk;
    const float* Wg = W + (size_t)(bn + lrow) * DIM + lk;

    float acc[16][4];   // [mi*8+ni][c0..c3]
#pragma unroll
    for (int i = 0; i < 16; i++)
#pragma unroll
        for (int j = 0; j < 4; j++) acc[i][j] = 0.0f;

    const int gid = lane >> 2;   // groupID 0..7
    const int tig = lane & 3;    // thread-in-group 0..3

    // ---- stage tile (buf, kt) ----
    auto stage = [&](int buf, int kt) {
        cp_async16(cvta_smem(&As[buf][lrow * GPAD + lk]),        Ag + kt);
        cp_async16(cvta_smem(&As[buf][(lrow + 64) * GPAD + lk]), Ag + (size_t)64 * DIM + kt);
        cp_async16(cvta_smem(&Bs[buf][lrow * GPAD + lk]),        Wg + kt);
        cp_async16(cvta_smem(&Bs[buf][(lrow + 64) * GPAD + lk]), Wg + (size_t)64 * DIM + kt);
        cp_commit();
    };

    stage(0, 0);

    int buf = 0;
    for (int kt = 0; kt < DIM; kt += BK, buf ^= 1) {
        if (kt + BK < DIM) {
            stage(buf ^ 1, kt + BK);
            asm volatile("cp.async.wait_group 1;");
        } else {
            asm volatile("cp.async.wait_group 0;");
        }
        __syncthreads();

        const float* as = &As[buf][0];
        const float* bs = &Bs[buf][0];

#pragma unroll
        for (int ks = 0; ks < BK; ks += 8) {
            // A fragments (2 m-tiles), fp32 then split
            uint32_t ah[2][4], al[2][4];
#pragma unroll
            for (int mi = 0; mi < 2; mi++) {
                const int r = wm + mi * 16 + gid;
                float f0 = as[r * GPAD + ks + tig];
                float f1 = as[(r + 8) * GPAD + ks + tig];
                float f2 = as[r * GPAD + ks + tig + 4];
                float f3 = as[(r + 8) * GPAD + ks + tig + 4];
                tf32_split(f0, ah[mi][0], al[mi][0]);
                tf32_split(f1, ah[mi][1], al[mi][1]);
                tf32_split(f2, ah[mi][2], al[mi][2]);
                tf32_split(f3, ah[mi][3], al[mi][3]);
            }
            // B fragments (8 n-tiles)
            uint32_t bh[8][2], bl[8][2];
#pragma unroll
            for (int ni = 0; ni < 8; ni++) {
                const int c = wn + ni * 8 + gid;
                float f0 = bs[c * GPAD + ks + tig];
                float f1 = bs[c * GPAD + ks + tig + 4];
                tf32_split(f0, bh[ni][0], bl[ni][0]);
                tf32_split(f1, bh[ni][1], bl[ni][1]);
            }
            // 3xTF32: hi*hi + hi*lo + lo*hi
#pragma unroll
            for (int mi = 0; mi < 2; mi++)
#pragma unroll
                for (int ni = 0; ni < 8; ni++) {
                    MMA_TF32(acc[mi * 8 + ni], ah[mi], bh[ni]);
                    MMA_TF32(acc[mi * 8 + ni], ah[mi], bl[ni]);
                    MMA_TF32(acc[mi * 8 + ni], al[mi], bh[ni]);
                }
        }
        __syncthreads();
    }

    // ---- epilogue: bias + store (two float2 per acc tile) ----
#pragma unroll
    for (int mi = 0; mi < 2; mi++) {
#pragma unroll
        for (int ni = 0; ni < 8; ni++) {
            const int row = bm + wm + mi * 16 + gid;
            const int col = bn + wn + ni * 8 + tig * 2;
            const float b0 = bias[col];
            const float b1 = bias[col + 1];
            const float* c = acc[mi * 8 + ni];
#pragma unroll
            for (int half = 0; half < 2; half++) {
                const int m = row + half * 8;
                const float v0 = c[half * 2 + 0] + b0;
                const float v1 = c[half * 2 + 1] + b1;
                if (SPLIT) {
                    const int b  = m / S_LEN;
                    const int s  = m % S_LEN;
                    const int h  = col / DHEAD;
                    const int dh = col % DHEAD;
                    float* dst = out + (((size_t)(b * NH + h)) * S_LEN + s) * DHEAD + dh;
                    dst[0] = v0;
                    dst[1] = v1;
                } else {
                    float* dst = out + (size_t)m * DIM + col;
                    dst[0] = v0;
                    dst[1] = v1;
                }
            }
        }
    }
}

// ---------------------------------------------------------------------------
// Flash attention (fp32, causal). One block per (q-tile of 64, head n).
// 256 threads as 16x16; each thread owns a 4x4 score tile and 4x4 O tile.
// SMEM: Q [64][68], K->P (reused) [64][68], V [64][68]  = 52224 B (dynamic).
// ---------------------------------------------------------------------------
#define FPAD 68

__global__ void __launch_bounds__(256) flash_attn()
{
    extern __shared__ float sm[];
    float* Qs  = sm;                 // 64*FPAD
    float* KPs = sm + 64 * FPAD;     // K tile, later reused as P
    float* Vs  = sm + 2 * 64 * FPAD;

    const int qt = blockIdx.x;       // 0..31
    const int n  = blockIdx.y;       // 0..31 (b*NH + h)
    const int tid = threadIdx.x;
    const int ty = tid >> 4;         // 0..15 -> rows ty*4..ty*4+3
    const int tx = tid & 15;         // 0..15 -> cols tx*4..tx*4+3

    const int lrow = tid >> 2;            // 0..63
    const int lcol = (tid & 3) * 16;      // 0,16,32,48

    const float* Qg = g_Q + ((size_t)n * S_LEN + qt * 64) * DHEAD;
    const float* Kg = g_K + (size_t)n * S_LEN * DHEAD;
    const float* Vg = g_V + (size_t)n * S_LEN * DHEAD;

    // Load Q tile, folding in softmax scale 1/sqrt(64) = 0.125
    const float scale = 0.125f;
#pragma unroll
    for (int i = 0; i < 4; i++) {
        float4 v = *(const float4*)(Qg + lrow * DHEAD + lcol + i * 4);
        float* d = Qs + lrow * FPAD + lcol + i * 4;
        d[0] = v.x * scale; d[1] = v.y * scale; d[2] = v.z * scale; d[3] = v.w * scale;
    }

    float m_old[4], l[4], o[4][4];
#pragma unroll
    for (int i = 0; i < 4; i++) {
        m_old[i] = -3.0e38f;
        l[i] = 0.0f;
#pragma unroll
        for (int j = 0; j < 4; j++) o[i][j] = 0.0f;
    }

    for (int kt = 0; kt <= qt; kt++) {
        __syncthreads();  // covers Q-load (iter 0) and previous P/V reads

        // Load K and V tiles
        const float* Kt = Kg + (size_t)(kt * 64) * DHEAD;
        const float* Vt = Vg + (size_t)(kt * 64) * DHEAD;
#pragma unroll
        for (int i = 0; i < 4; i++) {
            float4 kv = *(const float4*)(Kt + lrow * DHEAD + lcol + i * 4);
            *(float4*)(KPs + lrow * FPAD + lcol + i * 4) = kv;
            float4 vv = *(const float4*)(Vt + lrow * DHEAD + lcol + i * 4);
            *(float4*)(Vs + lrow * FPAD + lcol + i * 4) = vv;
        }
        __syncthreads();

        // S = Q * K^T   (4x4 per thread)
        float s[4][4];
#pragma unroll
        for (int i = 0; i < 4; i++)
#pragma unroll
            for (int j = 0; j < 4; j++) s[i][j] = 0.0f;

#pragma unroll 4
        for (int dd = 0; dd < DHEAD; dd += 4) {
            float4 q4[4], k4[4];
#pragma unroll
            for (int ri = 0; ri < 4; ri++)
                q4[ri] = *(const float4*)(Qs + (ty * 4 + ri) * FPAD + dd);
#pragma unroll
            for (int ci = 0; ci < 4; ci++)
                k4[ci] = *(const float4*)(KPs + (tx * 4 + ci) * FPAD + dd);
#pragma unroll
            for (int ri = 0; ri < 4; ri++) {
                const float* qf = (const float*)&q4[ri];
#pragma unroll
                for (int ci = 0; ci < 4; ci++) {
                    const float* kf = (const float*)&k4[ci];
                    s[ri][ci] = fmaf(qf[0], kf[0], s[ri][ci]);
                    s[ri][ci] = fmaf(qf[1], kf[1], s[ri][ci]);
                    s[ri][ci] = fmaf(qf[2], kf[2], s[ri][ci]);
                    s[ri][ci] = fmaf(qf[3], kf[3], s[ri][ci]);
                }
            }
        }

        // Causal mask on the diagonal tile
        if (kt == qt) {
#pragma unroll
            for (int ri = 0; ri < 4; ri++)
#pragma unroll
                for (int ci = 0; ci < 4; ci++)
                    if (tx * 4 + ci > ty * 4 + ri) s[ri][ci] = -3.0e38f;
        }

        // Online softmax per row (reduce across the 16 tx lanes)
#pragma unroll
        for (int ri = 0; ri < 4; ri++) {
            float mx = fmaxf(fmaxf(s[ri][0], s[ri][1]), fmaxf(s[ri][2], s[ri][3]));
#pragma unroll
            for (int off = 8; off >= 1; off >>= 1)
                mx = fmaxf(mx, __shfl_xor_sync(0xffffffffu, mx, off));
            const float m_new = fmaxf(m_old[ri], mx);
            const float alpha = __expf(m_old[ri] - m_new);
            float sum = 0.0f;
#pragma unroll
            for (int ci = 0; ci < 4; ci++) {
                const float p = __expf(s[ri][ci] - m_new);
                s[ri][ci] = p;
                sum += p;
            }
#pragma unroll
            for (int off = 8; off >= 1; off >>= 1)
                sum += __shfl_xor_sync(0xffffffffu, sum, off);
            l[ri] = l[ri] * alpha + sum;
            m_old[ri] = m_new;
#pragma unroll
            for (int j = 0; j < 4; j++) o[ri][j] *= alpha;
        }

        __syncthreads();  // done reading K tile; safe to overwrite with P

        // Stage P into SMEM (reuse K tile region)
#pragma unroll
        for (int ri = 0; ri < 4; ri++)
#pragma unroll
            for (int ci = 0; ci < 4; ci++)
                KPs[(ty * 4 + ri) * FPAD + tx * 4 + ci] = s[ri][ci];
        __syncthreads();

        // O += P * V   (4x4 per thread; cols here are head dims)
#pragma unroll 4
        for (int cc = 0; cc < 64; cc += 4) {
            float4 p4[4], v4[4];
#pragma unroll
            for (int ri = 0; ri < 4; ri++)
                p4[ri] = *(const float4*)(KPs + (ty * 4 + ri) * FPAD + cc);
#pragma unroll
            for (int cj = 0; cj < 4; cj++)
                v4[cj] = *(const float4*)(Vs + (cc + cj) * FPAD + tx * 4);
#pragma unroll
            for (int ri = 0; ri < 4; ri++) {
                const float* pf = (const float*)&p4[ri];
#pragma unroll
                for (int cj = 0; cj < 4; cj++) {
                    const float* vf = (const float*)&v4[cj];
                    o[ri][0] = fmaf(pf[cj], vf[0], o[ri][0]);
                    o[ri][1] = fmaf(pf[cj], vf[1], o[ri][1]);
                    o[ri][2] = fmaf(pf[cj], vf[2], o[ri][2]);
                    o[ri][3] = fmaf(pf[cj], vf[3], o[ri][3]);
                }
            }
        }
    }

    // Epilogue: normalize and store into concat-head layout [M_ROWS, DIM]
    const int b = n >> 4;
    const int h = n & 15;
#pragma unroll
    for (int ri = 0; ri < 4; ri++) {
        const float inv = 1.0f / l[ri];
        const int row_g = b * S_LEN + qt * 64 + ty * 4 + ri;
        const int col_g = h * DHEAD + tx * 4;
        float4 ov = make_float4(o[ri][0] * inv, o[ri][1] * inv,
                                o[ri][2] * inv, o[ri][3] * inv);
        *(float4*)(g_AO + (size_t)row_g * DIM + col_g) = ov;
    }
}

// ---------------------------------------------------------------------------
// kernel_launch
// Inputs (metadata order): x, mask, Wq, bq, Wk, bk, Wv, bv, Wo, bo
// mask is always tril in this problem; causality is hardcoded in flash_attn.
// ---------------------------------------------------------------------------
extern "C" void kernel_launch(void* const* d_in, const int* in_sizes, int n_in,
                              void* d_out, int out_size)
{
    const float* x  = (const float*)d_in[0];
    const float* Wq = (const float*)d_in[2];
    const float* bq = (const float*)d_in[3];
    const float* Wk = (const float*)d_in[4];
    const float* bk = (const float*)d_in[5];
    const float* Wv = (const float*)d_in[6];
    const float* bv = (const float*)d_in[7];
    const float* Wo = (const float*)d_in[8];
    const float* bo = (const float*)d_in[9];
    float* out = (float*)d_out;

    void *pQ, *pK, *pV, *pAO;
    cudaGetSymbolAddress(&pQ, g_Q);
    cudaGetSymbolAddress(&pK, g_K);
    cudaGetSymbolAddress(&pV, g_V);
    cudaGetSymbolAddress(&pAO, g_AO);

    const dim3 ggrid(DIM / BN, M_ROWS / BM);  // (8, 32)
    gemm_tf32<true><<<ggrid, 256>>>(x, Wq, bq, (float*)pQ);
    gemm_tf32<true><<<ggrid, 256>>>(x, Wk, bk, (float*)pK);
    gemm_tf32<true><<<ggrid, 256>>>(x, Wv, bv, (float*)pV);

    const int smem = 3 * 64 * FPAD * (int)sizeof(float);  // 52224
    cudaFuncSetAttribute(flash_attn, cudaFuncAttributeMaxDynamicSharedMemorySize, smem);
    flash_attn<<<dim3(S_LEN / 64, BATCH * NH), 256, smem>>>();

    gemm_tf32<false><<<ggrid, 256>>>((const float*)pAO, Wo, bo, out);
}

// round 3
// speedup vs baseline: 1.6022x; 1.2511x over previous
#include <cuda_runtime.h>
#include <math.h>
#include <stdint.h>

#define S_LEN 2048
#define DIM   1024
#define NH    16
#define DHEAD 64
#define BATCH 2
#define M_ROWS (BATCH * S_LEN)   // 4096

__device__ float g_Q[BATCH * NH * S_LEN * DHEAD];
__device__ float g_K[BATCH * NH * S_LEN * DHEAD];
__device__ float g_V[BATCH * NH * S_LEN * DHEAD];
__device__ float g_AO[M_ROWS * DIM];

// ---------------------------------------------------------------------------
// Helpers
// ---------------------------------------------------------------------------
__device__ __forceinline__ uint32_t cvta_smem(const void* p) {
    return (uint32_t)__cvta_generic_to_shared(p);
}
__device__ __forceinline__ void cp_async16(uint32_t dst, const void* src) {
    asm volatile("cp.async.cg.shared.global [%0], [%1], 16;" :: "r"(dst), "l"(src));
}
__device__ __forceinline__ void cp_commit() {
    asm volatile("cp.async.commit_group;");
}
__device__ __forceinline__ uint32_t f2tf32(float x) {
    uint32_t r;
    asm("cvt.rna.tf32.f32 %0, %1;" : "=r"(r) : "f"(x));
    return r;
}
__device__ __forceinline__ void tf32_split(float x, uint32_t& hi, uint32_t& lo) {
    hi = f2tf32(x);
    lo = f2tf32(x - __uint_as_float(hi));
}
// split to floats (bit patterns already tf32-rounded)
__device__ __forceinline__ void tf32_split_f(float x, float& hi, float& lo) {
    hi = __uint_as_float(f2tf32(x));
    lo = __uint_as_float(f2tf32(x - hi));
}

#define MMA_TF32(c, a, b)                                                     \
    asm volatile(                                                             \
        "mma.sync.aligned.m16n8k8.row.col.f32.tf32.tf32.f32 "                 \
        "{%0,%1,%2,%3}, {%4,%5,%6,%7}, {%8,%9}, {%0,%1,%2,%3};"               \
        : "+f"((c)[0]), "+f"((c)[1]), "+f"((c)[2]), "+f"((c)[3])              \
        : "r"((a)[0]), "r"((a)[1]), "r"((a)[2]), "r"((a)[3]),                 \
          "r"((b)[0]), "r"((b)[1]))

// ---------------------------------------------------------------------------
// TF32 tensor-core GEMM with 3xTF32 compensation (unchanged from round 2).
// ---------------------------------------------------------------------------
#define BM 128
#define BN 128
#define BK 16
#define GPAD 20

template <bool SPLIT>
__global__ void __launch_bounds__(256)
gemm_tf32(const float* __restrict__ A, const float* __restrict__ W,
          const float* __restrict__ bias, float* __restrict__ out)
{
    __shared__ float As[2][BM * GPAD];
    __shared__ float Bs[2][BN * GPAD];

    const int tid  = threadIdx.x;
    const int lane = tid & 31;
    const int wid  = tid >> 5;
    const int bm = blockIdx.y * BM;
    const int bn = blockIdx.x * BN;
    const int wm = (wid >> 1) * 32;
    const int wn = (wid & 1) * 64;

    const int lrow = tid >> 2;
    const int lk   = (tid & 3) * 4;
    const float* Ag = A + (size_t)(bm + lrow) * DIM + lk;
    const float* Wg = W + (size_t)(bn + lrow) * DIM + lk;

    float acc[16][4];
#pragma unroll
    for (int i = 0; i < 16; i++)
#pragma unroll
        for (int j = 0; j < 4; j++) acc[i][j] = 0.0f;

    const int gid = lane >> 2;
    const int tig = lane & 3;

    auto stage = [&](int buf, int kt) {
        cp_async16(cvta_smem(&As[buf][lrow * GPAD + lk]),        Ag + kt);
        cp_async16(cvta_smem(&As[buf][(lrow + 64) * GPAD + lk]), Ag + (size_t)64 * DIM + kt);
        cp_async16(cvta_smem(&Bs[buf][lrow * GPAD + lk]),        Wg + kt);
        cp_async16(cvta_smem(&Bs[buf][(lrow + 64) * GPAD + lk]), Wg + (size_t)64 * DIM + kt);
        cp_commit();
    };

    stage(0, 0);

    int buf = 0;
    for (int kt = 0; kt < DIM; kt += BK, buf ^= 1) {
        if (kt + BK < DIM) {
            stage(buf ^ 1, kt + BK);
            asm volatile("cp.async.wait_group 1;");
        } else {
            asm volatile("cp.async.wait_group 0;");
        }
        __syncthreads();

        const float* as = &As[buf][0];
        const float* bs = &Bs[buf][0];

#pragma unroll
        for (int ks = 0; ks < BK; ks += 8) {
            uint32_t ah[2][4], al[2][4];
#pragma unroll
            for (int mi = 0; mi < 2; mi++) {
                const int r = wm + mi * 16 + gid;
                tf32_split(as[r * GPAD + ks + tig],           ah[mi][0], al[mi][0]);
                tf32_split(as[(r + 8) * GPAD + ks + tig],     ah[mi][1], al[mi][1]);
                tf32_split(as[r * GPAD + ks + tig + 4],       ah[mi][2], al[mi][2]);
                tf32_split(as[(r + 8) * GPAD + ks + tig + 4], ah[mi][3], al[mi][3]);
            }
            uint32_t bh[8][2], bl[8][2];
#pragma unroll
            for (int ni = 0; ni < 8; ni++) {
                const int c = wn + ni * 8 + gid;
                tf32_split(bs[c * GPAD + ks + tig],     bh[ni][0], bl[ni][0]);
                tf32_split(bs[c * GPAD + ks + tig + 4], bh[ni][1], bl[ni][1]);
            }
#pragma unroll
            for (int mi = 0; mi < 2; mi++)
#pragma unroll
                for (int ni = 0; ni < 8; ni++) {
                    MMA_TF32(acc[mi * 8 + ni], ah[mi], bh[ni]);
                    MMA_TF32(acc[mi * 8 + ni], ah[mi], bl[ni]);
                    MMA_TF32(acc[mi * 8 + ni], al[mi], bh[ni]);
                }
        }
        __syncthreads();
    }

#pragma unroll
    for (int mi = 0; mi < 2; mi++) {
#pragma unroll
        for (int ni = 0; ni < 8; ni++) {
            const int row = bm + wm + mi * 16 + gid;
            const int col = bn + wn + ni * 8 + tig * 2;
            const float b0 = bias[col];
            const float b1 = bias[col + 1];
            const float* c = acc[mi * 8 + ni];
#pragma unroll
            for (int half = 0; half < 2; half++) {
                const int m = row + half * 8;
                const float v0 = c[half * 2 + 0] + b0;
                const float v1 = c[half * 2 + 1] + b1;
                if (SPLIT) {
                    const int b  = m / S_LEN;
                    const int s  = m % S_LEN;
                    const int h  = col / DHEAD;
                    const int dh = col % DHEAD;
                    float* dst = out + (((size_t)(b * NH + h)) * S_LEN + s) * DHEAD + dh;
                    dst[0] = v0;
                    dst[1] = v1;
                } else {
                    float* dst = out + (size_t)m * DIM + col;
                    dst[0] = v0;
                    dst[1] = v1;
                }
            }
        }
    }
}

// ---------------------------------------------------------------------------
// Flash attention on mma.tf32 (3xTF32 both GEMMs).
// Block = 64 q-rows, 4 warps (warp = 16 q-rows x 64 kpos), K-tiles of 64.
// SMEM tiles store interleaved (hi,lo) tf32 pairs, row stride KPAD=136
// (== 8 mod 64 -> conflict-free float2 fragment loads in both phases).
// ---------------------------------------------------------------------------
#define KPAD 136
#define FSM (3 * 64 * KPAD * 4)   // Khl, Vhl, Phl = 104448 B

__global__ void __launch_bounds__(128) flash_mma()
{
    extern __shared__ float sm[];
    float* Khl = sm;
    float* Vhl = sm + 64 * KPAD;
    float* Phl = sm + 2 * 64 * KPAD;

    const int qt   = (int)gridDim.x - 1 - (int)blockIdx.x;  // heavy blocks first
    const int n    = blockIdx.y;
    const int tid  = threadIdx.x;
    const int lane = tid & 31;
    const int w    = tid >> 5;
    const int gid  = lane >> 2;
    const int tig  = lane & 3;

    const float* Qg = g_Q + ((size_t)n * S_LEN + qt * 64) * DHEAD;
    const float* Kg = g_K + (size_t)n * S_LEN * DHEAD;
    const float* Vg = g_V + (size_t)n * S_LEN * DHEAD;

    const int r0 = w * 16 + gid;   // local q row (first)
    const int r1 = r0 + 8;

    // Q fragments in registers (fp32, pre-scaled)
    float qf[8][4];
#pragma unroll
    for (int ks = 0; ks < 8; ks++) {
        qf[ks][0] = Qg[r0 * DHEAD + ks * 8 + tig]     * 0.125f;
        qf[ks][1] = Qg[r1 * DHEAD + ks * 8 + tig]     * 0.125f;
        qf[ks][2] = Qg[r0 * DHEAD + ks * 8 + tig + 4] * 0.125f;
        qf[ks][3] = Qg[r1 * DHEAD + ks * 8 + tig + 4] * 0.125f;
    }

    float m0 = -1.0e30f, m1 = -1.0e30f, l0 = 0.0f, l1 = 0.0f;
    float o[8][4];
#pragma unroll
    for (int i = 0; i < 8; i++)
#pragma unroll
        for (int j = 0; j < 4; j++) o[i][j] = 0.0f;

    // staging indices: thread handles row srow, dh-half shalf (32 values)
    const int srow  = tid >> 1;
    const int shalf = (tid & 1) * 32;

    for (int kt = 0; kt <= qt; kt++) {
        __syncthreads();  // protect Khl/Vhl reuse vs previous iteration reads

        // ---- stage K, V tiles as interleaved (hi,lo) tf32 ----
        const float* Kt = Kg + (size_t)(kt * 64) * DHEAD;
        const float* Vt = Vg + (size_t)(kt * 64) * DHEAD;
#pragma unroll
        for (int i = 0; i < 8; i++) {
            float4 kv = *(const float4*)(Kt + srow * DHEAD + shalf + i * 4);
            float h0, lo0, h1, lo1, h2, lo2, h3, lo3;
            tf32_split_f(kv.x, h0, lo0); tf32_split_f(kv.y, h1, lo1);
            tf32_split_f(kv.z, h2, lo2); tf32_split_f(kv.w, h3, lo3);
            float* d = Khl + srow * KPAD + 2 * (shalf + i * 4);
            *(float4*)d       = make_float4(h0, lo0, h1, lo1);
            *(float4*)(d + 4) = make_float4(h2, lo2, h3, lo3);

            float4 vv = *(const float4*)(Vt + srow * DHEAD + shalf + i * 4);
            tf32_split_f(vv.x, h0, lo0); tf32_split_f(vv.y, h1, lo1);
            tf32_split_f(vv.z, h2, lo2); tf32_split_f(vv.w, h3, lo3);
            float* dv = Vhl + srow * KPAD + 2 * (shalf + i * 4);
            *(float4*)dv       = make_float4(h0, lo0, h1, lo1);
            *(float4*)(dv + 4) = make_float4(h2, lo2, h3, lo3);
        }
        __syncthreads();

        // ---- S = Q K^T  (per-warp 16x64, 8 n-tiles) ----
        float s[8][4];
#pragma unroll
        for (int i = 0; i < 8; i++)
#pragma unroll
            for (int j = 0; j < 4; j++) s[i][j] = 0.0f;

#pragma unroll
        for (int ks = 0; ks < 8; ks++) {
            uint32_t ah[4], al[4];
#pragma unroll
            for (int j = 0; j < 4; j++) tf32_split(qf[ks][j], ah[j], al[j]);
#pragma unroll
            for (int ni = 0; ni < 8; ni++) {
                const float* kp = Khl + (ni * 8 + gid) * KPAD + 2 * (ks * 8 + tig);
                float2 p0 = *(const float2*)kp;
                float2 p1 = *(const float2*)(kp + 8);
                uint32_t bh[2] = { __float_as_uint(p0.x), __float_as_uint(p1.x) };
                uint32_t bl[2] = { __float_as_uint(p0.y), __float_as_uint(p1.y) };
                MMA_TF32(s[ni], ah, bh);
                MMA_TF32(s[ni], ah, bl);
                MMA_TF32(s[ni], al, bh);
            }
        }

        // ---- causal mask on diagonal tile ----
        if (kt == qt) {
#pragma unroll
            for (int ni = 0; ni < 8; ni++) {
                const int c0 = ni * 8 + tig * 2;
                if (c0 > r0)     s[ni][0] = -1.0e30f;
                if (c0 + 1 > r0) s[ni][1] = -1.0e30f;
                if (c0 > r1)     s[ni][2] = -1.0e30f;
                if (c0 + 1 > r1) s[ni][3] = -1.0e30f;
            }
        }

        // ---- online softmax (rows r0, r1; reduce across quad = tig lanes) ----
        float mx0 = -1.0e30f, mx1 = -1.0e30f;
#pragma unroll
        for (int ni = 0; ni < 8; ni++) {
            mx0 = fmaxf(mx0, fmaxf(s[ni][0], s[ni][1]));
            mx1 = fmaxf(mx1, fmaxf(s[ni][2], s[ni][3]));
        }
        mx0 = fmaxf(mx0, __shfl_xor_sync(0xffffffffu, mx0, 1));
        mx0 = fmaxf(mx0, __shfl_xor_sync(0xffffffffu, mx0, 2));
        mx1 = fmaxf(mx1, __shfl_xor_sync(0xffffffffu, mx1, 1));
        mx1 = fmaxf(mx1, __shfl_xor_sync(0xffffffffu, mx1, 2));

        const float mn0 = fmaxf(m0, mx0);
        const float mn1 = fmaxf(m1, mx1);
        const float a0 = __expf(m0 - mn0);
        const float a1 = __expf(m1 - mn1);
        m0 = mn0; m1 = mn1;

        float sum0 = 0.0f, sum1 = 0.0f;
#pragma unroll
        for (int ni = 0; ni < 8; ni++) {
            s[ni][0] = __expf(s[ni][0] - mn0);
            s[ni][1] = __expf(s[ni][1] - mn0);
            s[ni][2] = __expf(s[ni][2] - mn1);
            s[ni][3] = __expf(s[ni][3] - mn1);
            sum0 += s[ni][0] + s[ni][1];
            sum1 += s[ni][2] + s[ni][3];
        }
        sum0 += __shfl_xor_sync(0xffffffffu, sum0, 1);
        sum0 += __shfl_xor_sync(0xffffffffu, sum0, 2);
        sum1 += __shfl_xor_sync(0xffffffffu, sum1, 1);
        sum1 += __shfl_xor_sync(0xffffffffu, sum1, 2);
        l0 = l0 * a0 + sum0;
        l1 = l1 * a1 + sum1;

#pragma unroll
        for (int ni = 0; ni < 8; ni++) {
            o[ni][0] *= a0; o[ni][1] *= a0;
            o[ni][2] *= a1; o[ni][3] *= a1;
        }

        // ---- stage P (hi,lo interleaved); produced+consumed within quad ----
#pragma unroll
        for (int ni = 0; ni < 8; ni++) {
            float h0, lo0, h1, lo1;
            tf32_split_f(s[ni][0], h0, lo0);
            tf32_split_f(s[ni][1], h1, lo1);
            *(float4*)(Phl + r0 * KPAD + 2 * (ni * 8 + tig * 2)) =
                make_float4(h0, lo0, h1, lo1);
            tf32_split_f(s[ni][2], h0, lo0);
            tf32_split_f(s[ni][3], h1, lo1);
            *(float4*)(Phl + r1 * KPAD + 2 * (ni * 8 + tig * 2)) =
                make_float4(h0, lo0, h1, lo1);
        }
        __syncwarp();

        // ---- O += P V  (k-dim = kpos 64, n-dim = dh 64) ----
#pragma unroll
        for (int ks = 0; ks < 8; ks++) {
            const float* pp0 = Phl + r0 * KPAD + 2 * (ks * 8 + tig);
            const float* pp1 = Phl + r1 * KPAD + 2 * (ks * 8 + tig);
            float2 fa0 = *(const float2*)pp0;
            float2 fa1 = *(const float2*)pp1;
            float2 fa2 = *(const float2*)(pp0 + 8);
            float2 fa3 = *(const float2*)(pp1 + 8);
            uint32_t ah[4] = { __float_as_uint(fa0.x), __float_as_uint(fa1.x),
                               __float_as_uint(fa2.x), __float_as_uint(fa3.x) };
            uint32_t al[4] = { __float_as_uint(fa0.y), __float_as_uint(fa1.y),
                               __float_as_uint(fa2.y), __float_as_uint(fa3.y) };
#pragma unroll
            for (int ni = 0; ni < 8; ni++) {
                const float* vp0 = Vhl + (ks * 8 + tig) * KPAD + 2 * (ni * 8 + gid);
                const float* vp1 = Vhl + (ks * 8 + tig + 4) * KPAD + 2 * (ni * 8 + gid);
                float2 p0 = *(const float2*)vp0;
                float2 p1 = *(const float2*)vp1;
                uint32_t bh[2] = { __float_as_uint(p0.x), __float_as_uint(p1.x) };
                uint32_t bl[2] = { __float_as_uint(p0.y), __float_as_uint(p1.y) };
                MMA_TF32(o[ni], ah, bh);
                MMA_TF32(o[ni], ah, bl);
                MMA_TF32(o[ni], al, bh);
            }
        }
    }

    // ---- epilogue: normalize, store concat-head ----
    const float inv0 = 1.0f / l0;
    const float inv1 = 1.0f / l1;
    const int b = n >> 4;
    const int h = n & 15;
    const int rowg0 = b * S_LEN + qt * 64 + r0;
    const int rowg1 = rowg0 + 8;
#pragma unroll
    for (int ni = 0; ni < 8; ni++) {
        const int col = h * DHEAD + ni * 8 + tig * 2;
        *(float2*)(g_AO + (size_t)rowg0 * DIM + col) =
            make_float2(o[ni][0] * inv0, o[ni][1] * inv0);
        *(float2*)(g_AO + (size_t)rowg1 * DIM + col) =
            make_float2(o[ni][2] * inv1, o[ni][3] * inv1);
    }
}

// ---------------------------------------------------------------------------
// kernel_launch: x, mask, Wq, bq, Wk, bk, Wv, bv, Wo, bo
// ---------------------------------------------------------------------------
extern "C" void kernel_launch(void* const* d_in, const int* in_sizes, int n_in,
                              void* d_out, int out_size)
{
    const float* x  = (const float*)d_in[0];
    const float* Wq = (const float*)d_in[2];
    const float* bq = (const float*)d_in[3];
    const float* Wk = (const float*)d_in[4];
    const float* bk = (const float*)d_in[5];
    const float* Wv = (const float*)d_in[6];
    const float* bv = (const float*)d_in[7];
    const float* Wo = (const float*)d_in[8];
    const float* bo = (const float*)d_in[9];
    float* out = (float*)d_out;

    void *pQ, *pK, *pV, *pAO;
    cudaGetSymbolAddress(&pQ, g_Q);
    cudaGetSymbolAddress(&pK, g_K);
    cudaGetSymbolAddress(&pV, g_V);
    cudaGetSymbolAddress(&pAO, g_AO);

    const dim3 ggrid(DIM / BN, M_ROWS / BM);  // (8, 32)
    gemm_tf32<true><<<ggrid, 256>>>(x, Wq, bq, (float*)pQ);
    gemm_tf32<true><<<ggrid, 256>>>(x, Wk, bk, (float*)pK);
    gemm_tf32<true><<<ggrid, 256>>>(x, Wv, bv, (float*)pV);

    cudaFuncSetAttribute(flash_mma, cudaFuncAttributeMaxDynamicSharedMemorySize, FSM);
    flash_mma<<<dim3(S_LEN / 64, BATCH * NH), 128, FSM>>>();

    gemm_tf32<false><<<ggrid, 256>>>((const float*)pAO, Wo, bo, out);
}

// round 4
// speedup vs baseline: 1.7869x; 1.1153x over previous
#include <cuda_runtime.h>
#include <math.h>
#include <stdint.h>

#define S_LEN 2048
#define DIM   1024
#define NH    16
#define DHEAD 64
#define BATCH 2
#define M_ROWS (BATCH * S_LEN)   // 4096

// Pre-split hi/lo tf32 planes (fp32 storage, tf32-valued).
__device__ float g_xh[M_ROWS * DIM],  g_xl[M_ROWS * DIM];
__device__ float g_Wqh[DIM * DIM], g_Wql[DIM * DIM];
__device__ float g_Wkh[DIM * DIM], g_Wkl[DIM * DIM];
__device__ float g_Wvh[DIM * DIM], g_Wvl[DIM * DIM];
__device__ float g_Woh[DIM * DIM], g_Wol[DIM * DIM];
// Q/K/V head-split planes [B*H, S, DH]
__device__ float g_Qh[M_ROWS * DIM], g_Ql[M_ROWS * DIM];
__device__ float g_Kh[M_ROWS * DIM], g_Kl[M_ROWS * DIM];
__device__ float g_Vh[M_ROWS * DIM], g_Vl[M_ROWS * DIM];
// attention output planes [M_ROWS, DIM] concat-head
__device__ float g_AOh[M_ROWS * DIM], g_AOl[M_ROWS * DIM];

// ---------------------------------------------------------------------------
// Helpers
// ---------------------------------------------------------------------------
__device__ __forceinline__ uint32_t cvta_smem(const void* p) {
    return (uint32_t)__cvta_generic_to_shared(p);
}
__device__ __forceinline__ void cp_async16(uint32_t dst, const void* src) {
    asm volatile("cp.async.cg.shared.global [%0], [%1], 16;" :: "r"(dst), "l"(src));
}
__device__ __forceinline__ void cp_commit() {
    asm volatile("cp.async.commit_group;");
}
__device__ __forceinline__ uint32_t f2tf32(float x) {
    uint32_t r;
    asm("cvt.rna.tf32.f32 %0, %1;" : "=r"(r) : "f"(x));
    return r;
}
__device__ __forceinline__ void tf32_split_f(float x, float& hi, float& lo) {
    hi = __uint_as_float(f2tf32(x));
    lo = __uint_as_float(f2tf32(x - hi));
}

#define MMA_TF32(c, a, b)                                                     \
    asm volatile(                                                             \
        "mma.sync.aligned.m16n8k8.row.col.f32.tf32.tf32.f32 "                 \
        "{%0,%1,%2,%3}, {%4,%5,%6,%7}, {%8,%9}, {%0,%1,%2,%3};"               \
        : "+f"((c)[0]), "+f"((c)[1]), "+f"((c)[2]), "+f"((c)[3])              \
        : "r"((a)[0]), "r"((a)[1]), "r"((a)[2]), "r"((a)[3]),                 \
          "r"((b)[0]), "r"((b)[1]))

// ---------------------------------------------------------------------------
// Prepass: split fp32 -> (hi, lo) tf32 planes. n4 = element count / 4.
// ---------------------------------------------------------------------------
__global__ void __launch_bounds__(256) split_plane(
    const float* __restrict__ in, float* __restrict__ oh,
    float* __restrict__ ol, int n4)
{
    const int i = blockIdx.x * blockDim.x + threadIdx.x;
    if (i >= n4) return;
    float4 v = ((const float4*)in)[i];
    float4 h, l;
    tf32_split_f(v.x, h.x, l.x);
    tf32_split_f(v.y, h.y, l.y);
    tf32_split_f(v.z, h.z, l.z);
    tf32_split_f(v.w, h.w, l.w);
    ((float4*)oh)[i] = h;
    ((float4*)ol)[i] = l;
}

// ---------------------------------------------------------------------------
// Split-free 3xTF32 GEMM on pre-split planes.
// out = A @ W^T + bias.  A planes [M x 1024], W planes [1024 x 1024].
// MODE 0: plain fp32 out [M x DIM].
// MODE 1: head-split dual-plane out (outh, outl).
// ---------------------------------------------------------------------------
#define BM 128
#define BN 128
#define BK 16
#define GPAD 20
#define GTILE (128 * GPAD)

template <int MODE>
__global__ void __launch_bounds__(256, 2)
gemm_pre(const float* __restrict__ Ahg, const float* __restrict__ Alg,
         const float* __restrict__ Bhg, const float* __restrict__ Blg,
         const float* __restrict__ bias,
         float* __restrict__ outh, float* __restrict__ outl)
{
    extern __shared__ float gsm[];
    float* Ahs = gsm;                 // 2 * GTILE
    float* Als = Ahs + 2 * GTILE;
    float* Bhs = Als + 2 * GTILE;
    float* Bls = Bhs + 2 * GTILE;

    const int tid  = threadIdx.x;
    const int lane = tid & 31;
    const int wid  = tid >> 5;
    const int bm = blockIdx.y * BM;
    const int bn = blockIdx.x * BN;
    const int wm = (wid >> 1) * 32;
    const int wn = (wid & 1) * 64;

    const int lrow = tid >> 2;
    const int lk   = (tid & 3) * 4;
    const float* Ah0 = Ahg + (size_t)(bm + lrow) * DIM + lk;
    const float* Al0 = Alg + (size_t)(bm + lrow) * DIM + lk;
    const float* Bh0 = Bhg + (size_t)(bn + lrow) * DIM + lk;
    const float* Bl0 = Blg + (size_t)(bn + lrow) * DIM + lk;

    float acc[16][4];
#pragma unroll
    for (int i = 0; i < 16; i++)
#pragma unroll
        for (int j = 0; j < 4; j++) acc[i][j] = 0.0f;

    const int gid = lane >> 2;
    const int tig = lane & 3;

    auto stage = [&](int buf, int kt) {
        const int o = buf * GTILE + lrow * GPAD + lk;
        const int o2 = o + 64 * GPAD;
        cp_async16(cvta_smem(Ahs + o),  Ah0 + kt);
        cp_async16(cvta_smem(Ahs + o2), Ah0 + (size_t)64 * DIM + kt);
        cp_async16(cvta_smem(Als + o),  Al0 + kt);
        cp_async16(cvta_smem(Als + o2), Al0 + (size_t)64 * DIM + kt);
        cp_async16(cvta_smem(Bhs + o),  Bh0 + kt);
        cp_async16(cvta_smem(Bhs + o2), Bh0 + (size_t)64 * DIM + kt);
        cp_async16(cvta_smem(Bls + o),  Bl0 + kt);
        cp_async16(cvta_smem(Bls + o2), Bl0 + (size_t)64 * DIM + kt);
        cp_commit();
    };

    stage(0, 0);

    int buf = 0;
    for (int kt = 0; kt < DIM; kt += BK, buf ^= 1) {
        if (kt + BK < DIM) {
            stage(buf ^ 1, kt + BK);
            asm volatile("cp.async.wait_group 1;");
        } else {
            asm volatile("cp.async.wait_group 0;");
        }
        __syncthreads();

        const float* ah_s = Ahs + buf * GTILE;
        const float* al_s = Als + buf * GTILE;
        const float* bh_s = Bhs + buf * GTILE;
        const float* bl_s = Bls + buf * GTILE;

#pragma unroll
        for (int ks = 0; ks < BK; ks += 8) {
            uint32_t ah[2][4], al[2][4];
#pragma unroll
            for (int mi = 0; mi < 2; mi++) {
                const int r = wm + mi * 16 + gid;
                ah[mi][0] = __float_as_uint(ah_s[r * GPAD + ks + tig]);
                ah[mi][1] = __float_as_uint(ah_s[(r + 8) * GPAD + ks + tig]);
                ah[mi][2] = __float_as_uint(ah_s[r * GPAD + ks + tig + 4]);
                ah[mi][3] = __float_as_uint(ah_s[(r + 8) * GPAD + ks + tig + 4]);
                al[mi][0] = __float_as_uint(al_s[r * GPAD + ks + tig]);
                al[mi][1] = __float_as_uint(al_s[(r + 8) * GPAD + ks + tig]);
                al[mi][2] = __float_as_uint(al_s[r * GPAD + ks + tig + 4]);
                al[mi][3] = __float_as_uint(al_s[(r + 8) * GPAD + ks + tig + 4]);
            }
            uint32_t bh[8][2], bl[8][2];
#pragma unroll
            for (int ni = 0; ni < 8; ni++) {
                const int c = wn + ni * 8 + gid;
                bh[ni][0] = __float_as_uint(bh_s[c * GPAD + ks + tig]);
                bh[ni][1] = __float_as_uint(bh_s[c * GPAD + ks + tig + 4]);
                bl[ni][0] = __float_as_uint(bl_s[c * GPAD + ks + tig]);
                bl[ni][1] = __float_as_uint(bl_s[c * GPAD + ks + tig + 4]);
            }
#pragma unroll
            for (int mi = 0; mi < 2; mi++)
#pragma unroll
                for (int ni = 0; ni < 8; ni++) {
                    MMA_TF32(acc[mi * 8 + ni], ah[mi], bh[ni]);
                    MMA_TF32(acc[mi * 8 + ni], ah[mi], bl[ni]);
                    MMA_TF32(acc[mi * 8 + ni], al[mi], bh[ni]);
                }
        }
        __syncthreads();
    }

#pragma unroll
    for (int mi = 0; mi < 2; mi++) {
#pragma unroll
        for (int ni = 0; ni < 8; ni++) {
            const int row = bm + wm + mi * 16 + gid;
            const int col = bn + wn + ni * 8 + tig * 2;
            const float b0 = bias[col];
            const float b1 = bias[col + 1];
            const float* c = acc[mi * 8 + ni];
#pragma unroll
            for (int half = 0; half < 2; half++) {
                const int m = row + half * 8;
                const float v0 = c[half * 2 + 0] + b0;
                const float v1 = c[half * 2 + 1] + b1;
                if (MODE == 1) {
                    const int b  = m / S_LEN;
                    const int s  = m % S_LEN;
                    const int h  = col / DHEAD;
                    const int dh = col % DHEAD;
                    const size_t off = (((size_t)(b * NH + h)) * S_LEN + s) * DHEAD + dh;
                    float h0, l0, h1, l1;
                    tf32_split_f(v0, h0, l0);
                    tf32_split_f(v1, h1, l1);
                    *(float2*)(outh + off) = make_float2(h0, h1);
                    *(float2*)(outl + off) = make_float2(l0, l1);
                } else {
                    float* dst = outh + (size_t)m * DIM + col;
                    dst[0] = v0;
                    dst[1] = v1;
                }
            }
        }
    }
}

// ---------------------------------------------------------------------------
// Flash attention on pre-split planes. Block = 64 q rows, 4 warps
// (warp = 16 q-rows x 64 kpos). QK^T: 3xTF32. PV: 2xTF32 (P rounded to tf32).
// SMEM planes: Kh/Kl [64x68], Vh/Vl [64x72], P [64x68]  = 89088 B.
// ---------------------------------------------------------------------------
#define KP 68
#define VP 72
#define FSM ((64 * (2 * KP + 2 * VP + KP)) * 4)

__global__ void __launch_bounds__(128) flash_mma()
{
    extern __shared__ float fsm_[];
    float* Khs = fsm_;
    float* Kls = Khs + 64 * KP;
    float* Vhs = Kls + 64 * KP;
    float* Vls = Vhs + 64 * VP;
    float* Ps  = Vls + 64 * VP;

    const int qt   = (int)gridDim.x - 1 - (int)blockIdx.x;
    const int n    = blockIdx.y;
    const int tid  = threadIdx.x;
    const int lane = tid & 31;
    const int w    = tid >> 5;
    const int gid  = lane >> 2;
    const int tig  = lane & 3;

    const size_t hbase = (size_t)n * S_LEN * DHEAD;
    const float* Qhg = g_Qh + hbase + (size_t)(qt * 64) * DHEAD;
    const float* Qlg = g_Ql + hbase + (size_t)(qt * 64) * DHEAD;

    const int r0 = w * 16 + gid;
    const int r1 = r0 + 8;

    // Q fragments pre-split in registers (scale 0.125 exact on both planes)
    uint32_t qh[8][4], ql[8][4];
#pragma unroll
    for (int ks = 0; ks < 8; ks++) {
        const int c0 = ks * 8 + tig;
        qh[ks][0] = __float_as_uint(Qhg[r0 * DHEAD + c0] * 0.125f);
        qh[ks][1] = __float_as_uint(Qhg[r1 * DHEAD + c0] * 0.125f);
        qh[ks][2] = __float_as_uint(Qhg[r0 * DHEAD + c0 + 4] * 0.125f);
        qh[ks][3] = __float_as_uint(Qhg[r1 * DHEAD + c0 + 4] * 0.125f);
        ql[ks][0] = __float_as_uint(Qlg[r0 * DHEAD + c0] * 0.125f);
        ql[ks][1] = __float_as_uint(Qlg[r1 * DHEAD + c0] * 0.125f);
        ql[ks][2] = __float_as_uint(Qlg[r0 * DHEAD + c0 + 4] * 0.125f);
        ql[ks][3] = __float_as_uint(Qlg[r1 * DHEAD + c0 + 4] * 0.125f);
    }

    float m0 = -1.0e30f, m1 = -1.0e30f, l0 = 0.0f, l1 = 0.0f;
    float o[8][4];
#pragma unroll
    for (int i = 0; i < 8; i++)
#pragma unroll
        for (int j = 0; j < 4; j++) o[i][j] = 0.0f;

    const int srow  = tid >> 1;
    const int shalf = (tid & 1) * 32;

    for (int kt = 0; kt <= qt; kt++) {
        __syncthreads();

        // ---- stage K/V planes via cp.async (no transforms) ----
        const size_t toff = hbase + (size_t)(kt * 64) * DHEAD;
        const float* sKh = g_Kh + toff + srow * DHEAD + shalf;
        const float* sKl = g_Kl + toff + srow * DHEAD + shalf;
        const float* sVh = g_Vh + toff + srow * DHEAD + shalf;
        const float* sVl = g_Vl + toff + srow * DHEAD + shalf;
        const uint32_t dKh = cvta_smem(Khs + srow * KP + shalf);
        const uint32_t dKl = cvta_smem(Kls + srow * KP + shalf);
        const uint32_t dVh = cvta_smem(Vhs + srow * VP + shalf);
        const uint32_t dVl = cvta_smem(Vls + srow * VP + shalf);
#pragma unroll
        for (int i = 0; i < 8; i++) {
            cp_async16(dKh + i * 16, sKh + i * 4);
            cp_async16(dKl + i * 16, sKl + i * 4);
            cp_async16(dVh + i * 16, sVh + i * 4);
            cp_async16(dVl + i * 16, sVl + i * 4);
        }
        cp_commit();
        asm volatile("cp.async.wait_group 0;");
        __syncthreads();

        // ---- S = Q K^T (3xTF32) ----
        float s[8][4];
#pragma unroll
        for (int i = 0; i < 8; i++)
#pragma unroll
            for (int j = 0; j < 4; j++) s[i][j] = 0.0f;

#pragma unroll
        for (int ks = 0; ks < 8; ks++) {
#pragma unroll
            for (int ni = 0; ni < 8; ni++) {
                const int kidx = (ni * 8 + gid) * KP + ks * 8 + tig;
                uint32_t bh[2] = { __float_as_uint(Khs[kidx]),
                                   __float_as_uint(Khs[kidx + 4]) };
                uint32_t bl[2] = { __float_as_uint(Kls[kidx]),
                                   __float_as_uint(Kls[kidx + 4]) };
                MMA_TF32(s[ni], qh[ks], bh);
                MMA_TF32(s[ni], qh[ks], bl);
                MMA_TF32(s[ni], ql[ks], bh);
            }
        }

        // ---- causal mask on diagonal tile ----
        if (kt == qt) {
#pragma unroll
            for (int ni = 0; ni < 8; ni++) {
                const int c0 = ni * 8 + tig * 2;
                if (c0 > r0)     s[ni][0] = -1.0e30f;
                if (c0 + 1 > r0) s[ni][1] = -1.0e30f;
                if (c0 > r1)     s[ni][2] = -1.0e30f;
                if (c0 + 1 > r1) s[ni][3] = -1.0e30f;
            }
        }

        // ---- online softmax ----
        float mx0 = -1.0e30f, mx1 = -1.0e30f;
#pragma unroll
        for (int ni = 0; ni < 8; ni++) {
            mx0 = fmaxf(mx0, fmaxf(s[ni][0], s[ni][1]));
            mx1 = fmaxf(mx1, fmaxf(s[ni][2], s[ni][3]));
        }
        mx0 = fmaxf(mx0, __shfl_xor_sync(0xffffffffu, mx0, 1));
        mx0 = fmaxf(mx0, __shfl_xor_sync(0xffffffffu, mx0, 2));
        mx1 = fmaxf(mx1, __shfl_xor_sync(0xffffffffu, mx1, 1));
        mx1 = fmaxf(mx1, __shfl_xor_sync(0xffffffffu, mx1, 2));

        const float mn0 = fmaxf(m0, mx0);
        const float mn1 = fmaxf(m1, mx1);
        const float a0 = __expf(m0 - mn0);
        const float a1 = __expf(m1 - mn1);
        m0 = mn0; m1 = mn1;

        float sum0 = 0.0f, sum1 = 0.0f;
#pragma unroll
        for (int ni = 0; ni < 8; ni++) {
            s[ni][0] = __expf(s[ni][0] - mn0);
            s[ni][1] = __expf(s[ni][1] - mn0);
            s[ni][2] = __expf(s[ni][2] - mn1);
            s[ni][3] = __expf(s[ni][3] - mn1);
            sum0 += s[ni][0] + s[ni][1];
            sum1 += s[ni][2] + s[ni][3];
        }
        sum0 += __shfl_xor_sync(0xffffffffu, sum0, 1);
        sum0 += __shfl_xor_sync(0xffffffffu, sum0, 2);
        sum1 += __shfl_xor_sync(0xffffffffu, sum1, 1);
        sum1 += __shfl_xor_sync(0xffffffffu, sum1, 2);
        l0 = l0 * a0 + sum0;
        l1 = l1 * a1 + sum1;

#pragma unroll
        for (int ni = 0; ni < 8; ni++) {
            o[ni][0] *= a0; o[ni][1] *= a0;
            o[ni][2] *= a1; o[ni][3] *= a1;
        }

        // ---- stage P (rounded to tf32); same-warp producer/consumer ----
#pragma unroll
        for (int ni = 0; ni < 8; ni++) {
            const int c = ni * 8 + tig * 2;
            *(float2*)(Ps + r0 * KP + c) = make_float2(
                __uint_as_float(f2tf32(s[ni][0])),
                __uint_as_float(f2tf32(s[ni][1])));
            *(float2*)(Ps + r1 * KP + c) = make_float2(
                __uint_as_float(f2tf32(s[ni][2])),
                __uint_as_float(f2tf32(s[ni][3])));
        }
        __syncwarp();

        // ---- O += P V (2xTF32) ----
#pragma unroll
        for (int ks = 0; ks < 8; ks++) {
            const int pc = ks * 8 + tig;
            uint32_t pa[4] = { __float_as_uint(Ps[r0 * KP + pc]),
                               __float_as_uint(Ps[r1 * KP + pc]),
                               __float_as_uint(Ps[r0 * KP + pc + 4]),
                               __float_as_uint(Ps[r1 * KP + pc + 4]) };
#pragma unroll
            for (int ni = 0; ni < 8; ni++) {
                const int v0 = (ks * 8 + tig) * VP + ni * 8 + gid;
                const int v1 = v0 + 4 * VP;
                uint32_t bh[2] = { __float_as_uint(Vhs[v0]),
                                   __float_as_uint(Vhs[v1]) };
                uint32_t bl[2] = { __float_as_uint(Vls[v0]),
                                   __float_as_uint(Vls[v1]) };
                MMA_TF32(o[ni], pa, bh);
                MMA_TF32(o[ni], pa, bl);
            }
        }
    }

    // ---- epilogue: normalize, split, store AO planes (concat-head) ----
    const float inv0 = 1.0f / l0;
    const float inv1 = 1.0f / l1;
    const int b = n >> 4;
    const int h = n & 15;
    const int rowg0 = b * S_LEN + qt * 64 + r0;
    const int rowg1 = rowg0 + 8;
#pragma unroll
    for (int ni = 0; ni < 8; ni++) {
        const int col = h * DHEAD + ni * 8 + tig * 2;
        float h0, lo0, h1, lo1;
        tf32_split_f(o[ni][0] * inv0, h0, lo0);
        tf32_split_f(o[ni][1] * inv0, h1, lo1);
        *(float2*)(g_AOh + (size_t)rowg0 * DIM + col) = make_float2(h0, h1);
        *(float2*)(g_AOl + (size_t)rowg0 * DIM + col) = make_float2(lo0, lo1);
        tf32_split_f(o[ni][2] * inv1, h0, lo0);
        tf32_split_f(o[ni][3] * inv1, h1, lo1);
        *(float2*)(g_AOh + (size_t)rowg1 * DIM + col) = make_float2(h0, h1);
        *(float2*)(g_AOl + (size_t)rowg1 * DIM + col) = make_float2(lo0, lo1);
    }
}

// ---------------------------------------------------------------------------
// kernel_launch: x, mask, Wq, bq, Wk, bk, Wv, bv, Wo, bo
// ---------------------------------------------------------------------------
extern "C" void kernel_launch(void* const* d_in, const int* in_sizes, int n_in,
                              void* d_out, int out_size)
{
    const float* x  = (const float*)d_in[0];
    const float* Wq = (const float*)d_in[2];
    const float* bq = (const float*)d_in[3];
    const float* Wk = (const float*)d_in[4];
    const float* bk = (const float*)d_in[5];
    const float* Wv = (const float*)d_in[6];
    const float* bv = (const float*)d_in[7];
    const float* Wo = (const float*)d_in[8];
    const float* bo = (const float*)d_in[9];
    float* out = (float*)d_out;

    float *xh, *xl, *Wqh, *Wql, *Wkh, *Wkl, *Wvh, *Wvl, *Woh, *Wol;
    float *Qh, *Ql, *Kh, *Kl, *Vh, *Vl, *AOh, *AOl;
    cudaGetSymbolAddress((void**)&xh,  g_xh);  cudaGetSymbolAddress((void**)&xl,  g_xl);
    cudaGetSymbolAddress((void**)&Wqh, g_Wqh); cudaGetSymbolAddress((void**)&Wql, g_Wql);
    cudaGetSymbolAddress((void**)&Wkh, g_Wkh); cudaGetSymbolAddress((void**)&Wkl, g_Wkl);
    cudaGetSymbolAddress((void**)&Wvh, g_Wvh); cudaGetSymbolAddress((void**)&Wvl, g_Wvl);
    cudaGetSymbolAddress((void**)&Woh, g_Woh); cudaGetSymbolAddress((void**)&Wol, g_Wol);
    cudaGetSymbolAddress((void**)&Qh,  g_Qh);  cudaGetSymbolAddress((void**)&Ql,  g_Ql);
    cudaGetSymbolAddress((void**)&Kh,  g_Kh);  cudaGetSymbolAddress((void**)&Kl,  g_Kl);
    cudaGetSymbolAddress((void**)&Vh,  g_Vh);  cudaGetSymbolAddress((void**)&Vl,  g_Vl);
    cudaGetSymbolAddress((void**)&AOh, g_AOh); cudaGetSymbolAddress((void**)&AOl, g_AOl);

    // Prepass splits
    split_plane<<<(M_ROWS * DIM / 4 + 255) / 256, 256>>>(x,  xh,  xl,  M_ROWS * DIM / 4);
    split_plane<<<(DIM * DIM / 4 + 255) / 256, 256>>>(Wq, Wqh, Wql, DIM * DIM / 4);
    split_plane<<<(DIM * DIM / 4 + 255) / 256, 256>>>(Wk, Wkh, Wkl, DIM * DIM / 4);
    split_plane<<<(DIM * DIM / 4 + 255) / 256, 256>>>(Wv, Wvh, Wvl, DIM * DIM / 4);
    split_plane<<<(DIM * DIM / 4 + 255) / 256, 256>>>(Wo, Woh, Wol, DIM * DIM / 4);

    const int gsmem = 8 * GTILE * (int)sizeof(float);  // 81920
    cudaFuncSetAttribute(gemm_pre<0>, cudaFuncAttributeMaxDynamicSharedMemorySize, gsmem);
    cudaFuncSetAttribute(gemm_pre<1>, cudaFuncAttributeMaxDynamicSharedMemorySize, gsmem);

    const dim3 ggrid(DIM / BN, M_ROWS / BM);  // (8, 32)
    gemm_pre<1><<<ggrid, 256, gsmem>>>(xh, xl, Wqh, Wql, bq, Qh, Ql);
    gemm_pre<1><<<ggrid, 256, gsmem>>>(xh, xl, Wkh, Wkl, bk, Kh, Kl);
    gemm_pre<1><<<ggrid, 256, gsmem>>>(xh, xl, Wvh, Wvl, bv, Vh, Vl);

    cudaFuncSetAttribute(flash_mma, cudaFuncAttributeMaxDynamicSharedMemorySize, FSM);
    flash_mma<<<dim3(S_LEN / 64, BATCH * NH), 128, FSM>>>();

    gemm_pre<0><<<ggrid, 256, gsmem>>>(AOh, AOl, Woh, Wol, bo, out, nullptr);
}

// round 5
// speedup vs baseline: 3.3597x; 1.8802x over previous
#include <cuda_runtime.h>
#include <cuda_bf16.h>
#include <math.h>
#include <stdint.h>

#define S_LEN 2048
#define DIM   1024
#define NH    16
#define DHEAD 64
#define BATCH 2
#define M_ROWS (BATCH * S_LEN)   // 4096
#define NW     (M_ROWS * DIM / 2)   // words per [M,DIM] bf16 plane
#define WW     (DIM * DIM / 2)      // words per weight plane

// bf16x2-packed hi/lo planes (k-pairs packed little-end: low half = even k)
__device__ uint32_t g_xh[NW],  g_xl[NW];
__device__ uint32_t g_Wqh[WW], g_Wql[WW];
__device__ uint32_t g_Wkh[WW], g_Wkl[WW];
__device__ uint32_t g_Wvh[WW], g_Wvl[WW];
__device__ uint32_t g_Woh[WW], g_Wol[WW];
// Q/K planes: head-split [B*H][S][DH/2 words] (Q pre-scaled by 0.125)
__device__ uint32_t g_Qh[NW], g_Ql[NW];
__device__ uint32_t g_Kh[NW], g_Kl[NW];
// V planes TRANSPOSED: [B*H][DH][S/2 words]
__device__ uint32_t g_Vth[NW], g_Vtl[NW];
// attention output planes [M][DIM/2 words] concat-head
__device__ uint32_t g_AOh[NW], g_AOl[NW];

// ---------------------------------------------------------------------------
// Helpers
// ---------------------------------------------------------------------------
__device__ __forceinline__ uint32_t cvta_smem(const void* p) {
    return (uint32_t)__cvta_generic_to_shared(p);
}
__device__ __forceinline__ void cp_async16(uint32_t dst, const void* src) {
    asm volatile("cp.async.cg.shared.global [%0], [%1], 16;" :: "r"(dst), "l"(src));
}
__device__ __forceinline__ void cp_commit() {
    asm volatile("cp.async.commit_group;");
}
// pack two fp32 -> bf16x2 word: low half = e0, high half = e1
__device__ __forceinline__ uint32_t packbf(float e0, float e1) {
    uint32_t r;
    asm("cvt.rn.bf16x2.f32 %0, %1, %2;" : "=r"(r) : "f"(e1), "f"(e0));
    return r;
}
// split pair into hi word + residual-lo word
__device__ __forceinline__ void split2(float e0, float e1, uint32_t& h, uint32_t& l) {
    h = packbf(e0, e1);
    float h0 = __uint_as_float(h << 16);
    float h1 = __uint_as_float(h & 0xFFFF0000u);
    l = packbf(e0 - h0, e1 - h1);
}

#define MMA_BF16(c, a, b)                                                     \
    asm volatile(                                                             \
        "mma.sync.aligned.m16n8k16.row.col.f32.bf16.bf16.f32 "                \
        "{%0,%1,%2,%3}, {%4,%5,%6,%7}, {%8,%9}, {%0,%1,%2,%3};"               \
        : "+f"((c)[0]), "+f"((c)[1]), "+f"((c)[2]), "+f"((c)[3])              \
        : "r"((a)[0]), "r"((a)[1]), "r"((a)[2]), "r"((a)[3]),                 \
          "r"((b)[0]), "r"((b)[1]))

// ---------------------------------------------------------------------------
// Prepass: fp32 -> packed bf16x2 (hi, lo) planes. n4 = elems/4.
// ---------------------------------------------------------------------------
__global__ void __launch_bounds__(256) split_bf16(
    const float* __restrict__ in, uint32_t* __restrict__ oh,
    uint32_t* __restrict__ ol, int n4)
{
    const int i = blockIdx.x * blockDim.x + threadIdx.x;
    if (i >= n4) return;
    float4 v = ((const float4*)in)[i];
    uint32_t h0, l0, h1, l1;
    split2(v.x, v.y, h0, l0);
    split2(v.z, v.w, h1, l1);
    ((uint2*)oh)[i] = make_uint2(h0, h1);
    ((uint2*)ol)[i] = make_uint2(l0, l1);
}

// ---------------------------------------------------------------------------
// 3xBF16 GEMM on packed planes. out = A @ W^T + bias.
// BM=BN=128, BK=32 bf16 (16 words), 256 threads, warp tile 32x64.
// MODE 0: fp32 out [M,DIM]   (final O projection)
// MODE 1: Q -> head-split bf16 planes, scaled by 0.125
// MODE 2: K -> head-split bf16 planes
// MODE 3: V -> TRANSPOSED head-split bf16 planes [n][dh][s]
// ---------------------------------------------------------------------------
#define BKW 16    // words per row per stage (BK=32 bf16)
#define AWP 20    // padded words per smem row
#define GTILEW (128 * AWP)

template <int MODE>
__global__ void __launch_bounds__(256, 2)
gemm_bf16(const uint32_t* __restrict__ Ahg, const uint32_t* __restrict__ Alg,
          const uint32_t* __restrict__ Bhg, const uint32_t* __restrict__ Blg,
          const float* __restrict__ bias,
          float* __restrict__ outf,
          uint32_t* __restrict__ outh, uint32_t* __restrict__ outl)
{
    extern __shared__ uint32_t gsm[];
    uint32_t* Ahs = gsm;                  // 2*GTILEW
    uint32_t* Als = Ahs + 2 * GTILEW;
    uint32_t* Bhs = Als + 2 * GTILEW;
    uint32_t* Bls = Bhs + 2 * GTILEW;

    const int tid  = threadIdx.x;
    const int lane = tid & 31;
    const int wid  = tid >> 5;
    const int bm = blockIdx.y * 128;
    const int bn = blockIdx.x * 128;
    const int wm = (wid >> 1) * 32;
    const int wn = (wid & 1) * 64;
    const int gid = lane >> 2;
    const int tig = lane & 3;

    const int lrow = tid >> 2;        // 0..63
    const int lkw  = (tid & 3) * 4;   // 0,4,8,12 words
    const uint32_t* Ah0 = Ahg + (size_t)(bm + lrow) * 512 + lkw;
    const uint32_t* Al0 = Alg + (size_t)(bm + lrow) * 512 + lkw;
    const uint32_t* Bh0 = Bhg + (size_t)(bn + lrow) * 512 + lkw;
    const uint32_t* Bl0 = Blg + (size_t)(bn + lrow) * 512 + lkw;

    float acc[16][4];
#pragma unroll
    for (int i = 0; i < 16; i++)
#pragma unroll
        for (int j = 0; j < 4; j++) acc[i][j] = 0.0f;

    auto stage = [&](int buf, int ktw) {
        const int o  = buf * GTILEW + lrow * AWP + lkw;
        const int o2 = o + 64 * AWP;
        cp_async16(cvta_smem(Ahs + o),  Ah0 + ktw);
        cp_async16(cvta_smem(Ahs + o2), Ah0 + 64 * 512 + ktw);
        cp_async16(cvta_smem(Als + o),  Al0 + ktw);
        cp_async16(cvta_smem(Als + o2), Al0 + 64 * 512 + ktw);
        cp_async16(cvta_smem(Bhs + o),  Bh0 + ktw);
        cp_async16(cvta_smem(Bhs + o2), Bh0 + 64 * 512 + ktw);
        cp_async16(cvta_smem(Bls + o),  Bl0 + ktw);
        cp_async16(cvta_smem(Bls + o2), Bl0 + 64 * 512 + ktw);
        cp_commit();
    };

    stage(0, 0);

    int buf = 0;
    for (int ktw = 0; ktw < 512; ktw += BKW, buf ^= 1) {
        if (ktw + BKW < 512) {
            stage(buf ^ 1, ktw + BKW);
            asm volatile("cp.async.wait_group 1;");
        } else {
            asm volatile("cp.async.wait_group 0;");
        }
        __syncthreads();

        const uint32_t* ah_s = Ahs + buf * GTILEW;
        const uint32_t* al_s = Als + buf * GTILEW;
        const uint32_t* bh_s = Bhs + buf * GTILEW;
        const uint32_t* bl_s = Bls + buf * GTILEW;

#pragma unroll
        for (int ks = 0; ks < 2; ks++) {
            uint32_t ah[2][4], al[2][4];
#pragma unroll
            for (int mi = 0; mi < 2; mi++) {
                const int r = wm + mi * 16 + gid;
                const int w0 = ks * 8 + tig;
                ah[mi][0] = ah_s[r * AWP + w0];
                ah[mi][1] = ah_s[(r + 8) * AWP + w0];
                ah[mi][2] = ah_s[r * AWP + w0 + 4];
                ah[mi][3] = ah_s[(r + 8) * AWP + w0 + 4];
                al[mi][0] = al_s[r * AWP + w0];
                al[mi][1] = al_s[(r + 8) * AWP + w0];
                al[mi][2] = al_s[r * AWP + w0 + 4];
                al[mi][3] = al_s[(r + 8) * AWP + w0 + 4];
            }
            uint32_t bh[8][2], bl[8][2];
#pragma unroll
            for (int ni = 0; ni < 8; ni++) {
                const int c = wn + ni * 8 + gid;
                const int w0 = ks * 8 + tig;
                bh[ni][0] = bh_s[c * AWP + w0];
                bh[ni][1] = bh_s[c * AWP + w0 + 4];
                bl[ni][0] = bl_s[c * AWP + w0];
                bl[ni][1] = bl_s[c * AWP + w0 + 4];
            }
#pragma unroll
            for (int mi = 0; mi < 2; mi++)
#pragma unroll
                for (int ni = 0; ni < 8; ni++) {
                    MMA_BF16(acc[mi * 8 + ni], ah[mi], bh[ni]);
                    MMA_BF16(acc[mi * 8 + ni], ah[mi], bl[ni]);
                    MMA_BF16(acc[mi * 8 + ni], al[mi], bh[ni]);
                }
        }
        __syncthreads();
    }

    // ---- epilogue ----
#pragma unroll
    for (int mi = 0; mi < 2; mi++) {
#pragma unroll
        for (int ni = 0; ni < 8; ni++) {
            const int row = bm + wm + mi * 16 + gid;
            const int col = bn + wn + ni * 8 + tig * 2;
            const float b0 = bias[col];
            const float b1 = bias[col + 1];
            const float* c = acc[mi * 8 + ni];
#pragma unroll
            for (int half = 0; half < 2; half++) {
                const int m = row + half * 8;
                float v0 = c[half * 2 + 0] + b0;
                float v1 = c[half * 2 + 1] + b1;
                if (MODE == 0) {
                    float* dst = outf + (size_t)m * DIM + col;
                    dst[0] = v0;
                    dst[1] = v1;
                } else if (MODE == 1 || MODE == 2) {
                    if (MODE == 1) { v0 *= 0.125f; v1 *= 0.125f; }
                    const int b  = m / S_LEN;
                    const int s  = m % S_LEN;
                    const int h  = col / DHEAD;
                    const int dw = (col % DHEAD) >> 1;
                    const size_t idx = ((size_t)(b * NH + h) * S_LEN + s) * 32 + dw;
                    uint32_t hw, lw;
                    split2(v0, v1, hw, lw);
                    outh[idx] = hw;
                    outl[idx] = lw;
                } else {  // MODE 3: V transposed
                    const int b  = m / S_LEN;
                    const int s  = m % S_LEN;
                    const int h  = col / DHEAD;
                    const int dh = col % DHEAD;
                    const int n  = b * NH + h;
                    __nv_bfloat16* VH = (__nv_bfloat16*)outh;
                    __nv_bfloat16* VL = (__nv_bfloat16*)outl;
                    __nv_bfloat16 h0 = __float2bfloat16(v0);
                    __nv_bfloat16 h1 = __float2bfloat16(v1);
                    __nv_bfloat16 l0 = __float2bfloat16(v0 - __bfloat162float(h0));
                    __nv_bfloat16 l1 = __float2bfloat16(v1 - __bfloat162float(h1));
                    const size_t base = ((size_t)n * DHEAD + dh) * S_LEN + s;
                    VH[base] = h0; VL[base] = l0;
                    VH[base + S_LEN] = h1; VL[base + S_LEN] = l1;
                }
            }
        }
    }
}

// ---------------------------------------------------------------------------
// Flash attention, all-bf16 3x emulation.
// Block = 64 q rows, 4 warps (warp = 16 q x 64 kpos). K tiles of 64.
// SMEM word planes (pad 36): Kh,Kl,Vh,Vl,Ph,Pl = 6*64*36*4 = 55296 B.
// ---------------------------------------------------------------------------
#define KWP 36
#define FSMW (6 * 64 * KWP)

__global__ void __launch_bounds__(128) flash_bf16()
{
    extern __shared__ uint32_t fsw[];
    uint32_t* Khs = fsw;
    uint32_t* Kls = Khs + 64 * KWP;
    uint32_t* Vhs = Kls + 64 * KWP;
    uint32_t* Vls = Vhs + 64 * KWP;
    uint32_t* Phs = Vls + 64 * KWP;
    uint32_t* Pls = Phs + 64 * KWP;

    const int qt   = (int)gridDim.x - 1 - (int)blockIdx.x;
    const int n    = blockIdx.y;
    const int tid  = threadIdx.x;
    const int lane = tid & 31;
    const int w    = tid >> 5;
    const int gid  = lane >> 2;
    const int tig  = lane & 3;

    const int r0 = w * 16 + gid;
    const int r1 = r0 + 8;

    // Q fragments (pre-scaled, pre-split words)
    const uint32_t* Qhg = g_Qh + ((size_t)n * S_LEN + qt * 64) * 32;
    const uint32_t* Qlg = g_Ql + ((size_t)n * S_LEN + qt * 64) * 32;
    uint32_t qh[4][4], ql[4][4];
#pragma unroll
    for (int ks = 0; ks < 4; ks++) {
        const int w0 = ks * 8 + tig;
        qh[ks][0] = Qhg[r0 * 32 + w0];
        qh[ks][1] = Qhg[r1 * 32 + w0];
        qh[ks][2] = Qhg[r0 * 32 + w0 + 4];
        qh[ks][3] = Qhg[r1 * 32 + w0 + 4];
        ql[ks][0] = Qlg[r0 * 32 + w0];
        ql[ks][1] = Qlg[r1 * 32 + w0];
        ql[ks][2] = Qlg[r0 * 32 + w0 + 4];
        ql[ks][3] = Qlg[r1 * 32 + w0 + 4];
    }

    float m0 = -1.0e30f, m1 = -1.0e30f, l0 = 0.0f, l1 = 0.0f;
    float o[8][4];
#pragma unroll
    for (int i = 0; i < 8; i++)
#pragma unroll
        for (int j = 0; j < 4; j++) o[i][j] = 0.0f;

    const int srow = tid >> 1;           // 0..63
    const int soff = (tid & 1) * 16;     // words

    const uint32_t* Khg = g_Kh + (size_t)n * S_LEN * 32;
    const uint32_t* Klg = g_Kl + (size_t)n * S_LEN * 32;
    const uint32_t* Vhg = g_Vth + (size_t)n * DHEAD * (S_LEN / 2);
    const uint32_t* Vlg = g_Vtl + (size_t)n * DHEAD * (S_LEN / 2);

    for (int kt = 0; kt <= qt; kt++) {
        __syncthreads();

        // ---- stage K (natural) and V (transposed) tiles ----
        const uint32_t* sKh = Khg + (size_t)(kt * 64 + srow) * 32 + soff;
        const uint32_t* sKl = Klg + (size_t)(kt * 64 + srow) * 32 + soff;
        const uint32_t* sVh = Vhg + (size_t)srow * (S_LEN / 2) + kt * 32 + soff;
        const uint32_t* sVl = Vlg + (size_t)srow * (S_LEN / 2) + kt * 32 + soff;
        const uint32_t dK = cvta_smem(Khs + srow * KWP + soff);
        const uint32_t dKl_ = cvta_smem(Kls + srow * KWP + soff);
        const uint32_t dV = cvta_smem(Vhs + srow * KWP + soff);
        const uint32_t dVl_ = cvta_smem(Vls + srow * KWP + soff);
#pragma unroll
        for (int i = 0; i < 4; i++) {
            cp_async16(dK + i * 16,   sKh + i * 4);
            cp_async16(dKl_ + i * 16, sKl + i * 4);
            cp_async16(dV + i * 16,   sVh + i * 4);
            cp_async16(dVl_ + i * 16, sVl + i * 4);
        }
        cp_commit();
        asm volatile("cp.async.wait_group 0;");
        __syncthreads();

        // ---- S = Q K^T (3xBF16) ----
        float s[8][4];
#pragma unroll
        for (int i = 0; i < 8; i++)
#pragma unroll
            for (int j = 0; j < 4; j++) s[i][j] = 0.0f;

#pragma unroll
        for (int ks = 0; ks < 4; ks++) {
#pragma unroll
            for (int ni = 0; ni < 8; ni++) {
                const int kw = (ni * 8 + gid) * KWP + ks * 8 + tig;
                uint32_t bh[2] = { Khs[kw], Khs[kw + 4] };
                uint32_t bl[2] = { Kls[kw], Kls[kw + 4] };
                MMA_BF16(s[ni], qh[ks], bh);
                MMA_BF16(s[ni], qh[ks], bl);
                MMA_BF16(s[ni], ql[ks], bh);
            }
        }

        // ---- causal mask on diagonal tile ----
        if (kt == qt) {
#pragma unroll
            for (int ni = 0; ni < 8; ni++) {
                const int c0 = ni * 8 + tig * 2;
                if (c0 > r0)     s[ni][0] = -1.0e30f;
                if (c0 + 1 > r0) s[ni][1] = -1.0e30f;
                if (c0 > r1)     s[ni][2] = -1.0e30f;
                if (c0 + 1 > r1) s[ni][3] = -1.0e30f;
            }
        }

        // ---- online softmax ----
        float mx0 = -1.0e30f, mx1 = -1.0e30f;
#pragma unroll
        for (int ni = 0; ni < 8; ni++) {
            mx0 = fmaxf(mx0, fmaxf(s[ni][0], s[ni][1]));
            mx1 = fmaxf(mx1, fmaxf(s[ni][2], s[ni][3]));
        }
        mx0 = fmaxf(mx0, __shfl_xor_sync(0xffffffffu, mx0, 1));
        mx0 = fmaxf(mx0, __shfl_xor_sync(0xffffffffu, mx0, 2));
        mx1 = fmaxf(mx1, __shfl_xor_sync(0xffffffffu, mx1, 1));
        mx1 = fmaxf(mx1, __shfl_xor_sync(0xffffffffu, mx1, 2));

        const float mn0 = fmaxf(m0, mx0);
        const float mn1 = fmaxf(m1, mx1);
        const float a0 = __expf(m0 - mn0);
        const float a1 = __expf(m1 - mn1);
        m0 = mn0; m1 = mn1;

        float sum0 = 0.0f, sum1 = 0.0f;
#pragma unroll
        for (int ni = 0; ni < 8; ni++) {
            s[ni][0] = __expf(s[ni][0] - mn0);
            s[ni][1] = __expf(s[ni][1] - mn0);
            s[ni][2] = __expf(s[ni][2] - mn1);
            s[ni][3] = __expf(s[ni][3] - mn1);
            sum0 += s[ni][0] + s[ni][1];
            sum1 += s[ni][2] + s[ni][3];
        }
        sum0 += __shfl_xor_sync(0xffffffffu, sum0, 1);
        sum0 += __shfl_xor_sync(0xffffffffu, sum0, 2);
        sum1 += __shfl_xor_sync(0xffffffffu, sum1, 1);
        sum1 += __shfl_xor_sync(0xffffffffu, sum1, 2);
        l0 = l0 * a0 + sum0;
        l1 = l1 * a1 + sum1;

#pragma unroll
        for (int ni = 0; ni < 8; ni++) {
            o[ni][0] *= a0; o[ni][1] *= a0;
            o[ni][2] *= a1; o[ni][3] *= a1;
        }

        // ---- stage P as bf16 hi/lo words (same-warp producer/consumer) ----
#pragma unroll
        for (int ni = 0; ni < 8; ni++) {
            const int wi0 = r0 * KWP + ni * 4 + tig;
            const int wi1 = r1 * KWP + ni * 4 + tig;
            uint32_t hw, lw;
            split2(s[ni][0], s[ni][1], hw, lw);
            Phs[wi0] = hw; Pls[wi0] = lw;
            split2(s[ni][2], s[ni][3], hw, lw);
            Phs[wi1] = hw; Pls[wi1] = lw;
        }
        __syncwarp();

        // ---- O += P V (3xBF16) ----
#pragma unroll
        for (int ks = 0; ks < 4; ks++) {
            const int w0 = ks * 8 + tig;
            uint32_t ph[4] = { Phs[r0 * KWP + w0], Phs[r1 * KWP + w0],
                               Phs[r0 * KWP + w0 + 4], Phs[r1 * KWP + w0 + 4] };
            uint32_t pl[4] = { Pls[r0 * KWP + w0], Pls[r1 * KWP + w0],
                               Pls[r0 * KWP + w0 + 4], Pls[r1 * KWP + w0 + 4] };
#pragma unroll
            for (int ni = 0; ni < 8; ni++) {
                const int vw = (ni * 8 + gid) * KWP + ks * 8 + tig;
                uint32_t bh[2] = { Vhs[vw], Vhs[vw + 4] };
                uint32_t bl[2] = { Vls[vw], Vls[vw + 4] };
                MMA_BF16(o[ni], ph, bh);
                MMA_BF16(o[ni], ph, bl);
                MMA_BF16(o[ni], pl, bh);
            }
        }
    }

    // ---- epilogue: normalize, split, store AO word planes (concat-head) ----
    const float inv0 = 1.0f / l0;
    const float inv1 = 1.0f / l1;
    const int b = n >> 4;
    const int h = n & 15;
    const int rowg0 = b * S_LEN + qt * 64 + r0;
    const int rowg1 = rowg0 + 8;
#pragma unroll
    for (int ni = 0; ni < 8; ni++) {
        const int cw = h * 32 + ni * 4 + tig;   // word col
        uint32_t hw, lw;
        split2(o[ni][0] * inv0, o[ni][1] * inv0, hw, lw);
        g_AOh[(size_t)rowg0 * 512 + cw] = hw;
        g_AOl[(size_t)rowg0 * 512 + cw] = lw;
        split2(o[ni][2] * inv1, o[ni][3] * inv1, hw, lw);
        g_AOh[(size_t)rowg1 * 512 + cw] = hw;
        g_AOl[(size_t)rowg1 * 512 + cw] = lw;
    }
}

// ---------------------------------------------------------------------------
// kernel_launch: x, mask, Wq, bq, Wk, bk, Wv, bv, Wo, bo
// ---------------------------------------------------------------------------
extern "C" void kernel_launch(void* const* d_in, const int* in_sizes, int n_in,
                              void* d_out, int out_size)
{
    const float* x  = (const float*)d_in[0];
    const float* Wq = (const float*)d_in[2];
    const float* bq = (const float*)d_in[3];
    const float* Wk = (const float*)d_in[4];
    const float* bk = (const float*)d_in[5];
    const float* Wv = (const float*)d_in[6];
    const float* bv = (const float*)d_in[7];
    const float* Wo = (const float*)d_in[8];
    const float* bo = (const float*)d_in[9];
    float* out = (float*)d_out;

    uint32_t *xh, *xl, *Wqh, *Wql, *Wkh, *Wkl, *Wvh, *Wvl, *Woh, *Wol;
    uint32_t *Qh, *Ql, *Kh, *Kl, *Vth, *Vtl, *AOh, *AOl;
    cudaGetSymbolAddress((void**)&xh,  g_xh);  cudaGetSymbolAddress((void**)&xl,  g_xl);
    cudaGetSymbolAddress((void**)&Wqh, g_Wqh); cudaGetSymbolAddress((void**)&Wql, g_Wql);
    cudaGetSymbolAddress((void**)&Wkh, g_Wkh); cudaGetSymbolAddress((void**)&Wkl, g_Wkl);
    cudaGetSymbolAddress((void**)&Wvh, g_Wvh); cudaGetSymbolAddress((void**)&Wvl, g_Wvl);
    cudaGetSymbolAddress((void**)&Woh, g_Woh); cudaGetSymbolAddress((void**)&Wol, g_Wol);
    cudaGetSymbolAddress((void**)&Qh,  g_Qh);  cudaGetSymbolAddress((void**)&Ql,  g_Ql);
    cudaGetSymbolAddress((void**)&Kh,  g_Kh);  cudaGetSymbolAddress((void**)&Kl,  g_Kl);
    cudaGetSymbolAddress((void**)&Vth, g_Vth); cudaGetSymbolAddress((void**)&Vtl, g_Vtl);
    cudaGetSymbolAddress((void**)&AOh, g_AOh); cudaGetSymbolAddress((void**)&AOl, g_AOl);

    // Prepass splits
    split_bf16<<<(M_ROWS * DIM / 4 + 255) / 256, 256>>>(x,  xh,  xl,  M_ROWS * DIM / 4);
    split_bf16<<<(DIM * DIM / 4 + 255) / 256, 256>>>(Wq, Wqh, Wql, DIM * DIM / 4);
    split_bf16<<<(DIM * DIM / 4 + 255) / 256, 256>>>(Wk, Wkh, Wkl, DIM * DIM / 4);
    split_bf16<<<(DIM * DIM / 4 + 255) / 256, 256>>>(Wv, Wvh, Wvl, DIM * DIM / 4);
    split_bf16<<<(DIM * DIM / 4 + 255) / 256, 256>>>(Wo, Woh, Wol, DIM * DIM / 4);

    const int gsmem = 8 * GTILEW * (int)sizeof(uint32_t);  // 81920
    cudaFuncSetAttribute(gemm_bf16<0>, cudaFuncAttributeMaxDynamicSharedMemorySize, gsmem);
    cudaFuncSetAttribute(gemm_bf16<1>, cudaFuncAttributeMaxDynamicSharedMemorySize, gsmem);
    cudaFuncSetAttribute(gemm_bf16<2>, cudaFuncAttributeMaxDynamicSharedMemorySize, gsmem);
    cudaFuncSetAttribute(gemm_bf16<3>, cudaFuncAttributeMaxDynamicSharedMemorySize, gsmem);

    const dim3 ggrid(DIM / 128, M_ROWS / 128);  // (8, 32)
    gemm_bf16<1><<<ggrid, 256, gsmem>>>(xh, xl, Wqh, Wql, bq, nullptr, Qh, Ql);
    gemm_bf16<2><<<ggrid, 256, gsmem>>>(xh, xl, Wkh, Wkl, bk, nullptr, Kh, Kl);
    gemm_bf16<3><<<ggrid, 256, gsmem>>>(xh, xl, Wvh, Wvl, bv, nullptr, Vth, Vtl);

    const int fsmem = FSMW * (int)sizeof(uint32_t);  // 55296
    cudaFuncSetAttribute(flash_bf16, cudaFuncAttributeMaxDynamicSharedMemorySize, fsmem);
    flash_bf16<<<dim3(S_LEN / 64, BATCH * NH), 128, fsmem>>>();

    gemm_bf16<0><<<ggrid, 256, gsmem>>>(AOh, AOl, Woh, Wol, bo, out, nullptr, nullptr);
}

// round 6
// speedup vs baseline: 3.5687x; 1.0622x over previous
#include <cuda_runtime.h>
#include <cuda_bf16.h>
#include <math.h>
#include <stdint.h>

#define S_LEN 2048
#define DIM   1024
#define NH    16
#define DHEAD 64
#define BATCH 2
#define M_ROWS (BATCH * S_LEN)   // 4096
#define NW     (M_ROWS * DIM / 2)   // words per [M,DIM] bf16 plane
#define WW     (DIM * DIM / 2)      // words per weight plane

// bf16x2-packed hi/lo planes (k-pairs packed little-end: low half = even k)
__device__ uint32_t g_xh[NW],  g_xl[NW];
__device__ uint32_t g_Wqh[WW], g_Wql[WW];
__device__ uint32_t g_Wkh[WW], g_Wkl[WW];
__device__ uint32_t g_Wvh[WW], g_Wvl[WW];
__device__ uint32_t g_Woh[WW], g_Wol[WW];
// Q/K planes: head-split [B*H][S][DH/2 words] (Q pre-scaled by 0.125)
__device__ uint32_t g_Qh[NW], g_Ql[NW];
__device__ uint32_t g_Kh[NW], g_Kl[NW];
// V planes TRANSPOSED: [B*H][DH][S/2 words]
__device__ uint32_t g_Vth[NW], g_Vtl[NW];
// attention output planes [M][DIM/2 words] concat-head
__device__ uint32_t g_AOh[NW], g_AOl[NW];

// ---------------------------------------------------------------------------
// Helpers
// ---------------------------------------------------------------------------
__device__ __forceinline__ uint32_t cvta_smem(const void* p) {
    return (uint32_t)__cvta_generic_to_shared(p);
}
__device__ __forceinline__ void cp_async16(uint32_t dst, const void* src) {
    asm volatile("cp.async.cg.shared.global [%0], [%1], 16;" :: "r"(dst), "l"(src));
}
__device__ __forceinline__ void cp_commit() {
    asm volatile("cp.async.commit_group;");
}
// pack two fp32 -> bf16x2 word: low half = e0, high half = e1
__device__ __forceinline__ uint32_t packbf(float e0, float e1) {
    uint32_t r;
    asm("cvt.rn.bf16x2.f32 %0, %1, %2;" : "=r"(r) : "f"(e1), "f"(e0));
    return r;
}
// split pair into hi word + residual-lo word
__device__ __forceinline__ void split2(float e0, float e1, uint32_t& h, uint32_t& l) {
    h = packbf(e0, e1);
    float h0 = __uint_as_float(h << 16);
    float h1 = __uint_as_float(h & 0xFFFF0000u);
    l = packbf(e0 - h0, e1 - h1);
}

#define MMA_BF16(c, a, b)                                                     \
    asm volatile(                                                             \
        "mma.sync.aligned.m16n8k16.row.col.f32.bf16.bf16.f32 "                \
        "{%0,%1,%2,%3}, {%4,%5,%6,%7}, {%8,%9}, {%0,%1,%2,%3};"               \
        : "+f"((c)[0]), "+f"((c)[1]), "+f"((c)[2]), "+f"((c)[3])              \
        : "r"((a)[0]), "r"((a)[1]), "r"((a)[2]), "r"((a)[3]),                 \
          "r"((b)[0]), "r"((b)[1]))

// ---------------------------------------------------------------------------
// Prepass: fp32 -> packed bf16x2 (hi, lo) planes. n4 = elems/4.
// ---------------------------------------------------------------------------
__global__ void __launch_bounds__(256) split_bf16(
    const float* __restrict__ in, uint32_t* __restrict__ oh,
    uint32_t* __restrict__ ol, int n4)
{
    const int i = blockIdx.x * blockDim.x + threadIdx.x;
    if (i >= n4) return;
    float4 v = ((const float4*)in)[i];
    uint32_t h0, l0, h1, l1;
    split2(v.x, v.y, h0, l0);
    split2(v.z, v.w, h1, l1);
    ((uint2*)oh)[i] = make_uint2(h0, h1);
    ((uint2*)ol)[i] = make_uint2(l0, l1);
}

// ---------------------------------------------------------------------------
// 3xBF16 GEMM on packed planes (unchanged from round 5).
// ---------------------------------------------------------------------------
#define BKW 16
#define AWP 20
#define GTILEW (128 * AWP)

template <int MODE>
__global__ void __launch_bounds__(256, 2)
gemm_bf16(const uint32_t* __restrict__ Ahg, const uint32_t* __restrict__ Alg,
          const uint32_t* __restrict__ Bhg, const uint32_t* __restrict__ Blg,
          const float* __restrict__ bias,
          float* __restrict__ outf,
          uint32_t* __restrict__ outh, uint32_t* __restrict__ outl)
{
    extern __shared__ uint32_t gsm[];
    uint32_t* Ahs = gsm;
    uint32_t* Als = Ahs + 2 * GTILEW;
    uint32_t* Bhs = Als + 2 * GTILEW;
    uint32_t* Bls = Bhs + 2 * GTILEW;

    const int tid  = threadIdx.x;
    const int lane = tid & 31;
    const int wid  = tid >> 5;
    const int bm = blockIdx.y * 128;
    const int bn = blockIdx.x * 128;
    const int wm = (wid >> 1) * 32;
    const int wn = (wid & 1) * 64;
    const int gid = lane >> 2;
    const int tig = lane & 3;

    const int lrow = tid >> 2;
    const int lkw  = (tid & 3) * 4;
    const uint32_t* Ah0 = Ahg + (size_t)(bm + lrow) * 512 + lkw;
    const uint32_t* Al0 = Alg + (size_t)(bm + lrow) * 512 + lkw;
    const uint32_t* Bh0 = Bhg + (size_t)(bn + lrow) * 512 + lkw;
    const uint32_t* Bl0 = Blg + (size_t)(bn + lrow) * 512 + lkw;

    float acc[16][4];
#pragma unroll
    for (int i = 0; i < 16; i++)
#pragma unroll
        for (int j = 0; j < 4; j++) acc[i][j] = 0.0f;

    auto stage = [&](int buf, int ktw) {
        const int o  = buf * GTILEW + lrow * AWP + lkw;
        const int o2 = o + 64 * AWP;
        cp_async16(cvta_smem(Ahs + o),  Ah0 + ktw);
        cp_async16(cvta_smem(Ahs + o2), Ah0 + 64 * 512 + ktw);
        cp_async16(cvta_smem(Als + o),  Al0 + ktw);
        cp_async16(cvta_smem(Als + o2), Al0 + 64 * 512 + ktw);
        cp_async16(cvta_smem(Bhs + o),  Bh0 + ktw);
        cp_async16(cvta_smem(Bhs + o2), Bh0 + 64 * 512 + ktw);
        cp_async16(cvta_smem(Bls + o),  Bl0 + ktw);
        cp_async16(cvta_smem(Bls + o2), Bl0 + 64 * 512 + ktw);
        cp_commit();
    };

    stage(0, 0);

    int buf = 0;
    for (int ktw = 0; ktw < 512; ktw += BKW, buf ^= 1) {
        if (ktw + BKW < 512) {
            stage(buf ^ 1, ktw + BKW);
            asm volatile("cp.async.wait_group 1;");
        } else {
            asm volatile("cp.async.wait_group 0;");
        }
        __syncthreads();

        const uint32_t* ah_s = Ahs + buf * GTILEW;
        const uint32_t* al_s = Als + buf * GTILEW;
        const uint32_t* bh_s = Bhs + buf * GTILEW;
        const uint32_t* bl_s = Bls + buf * GTILEW;

#pragma unroll
        for (int ks = 0; ks < 2; ks++) {
            uint32_t ah[2][4], al[2][4];
#pragma unroll
            for (int mi = 0; mi < 2; mi++) {
                const int r = wm + mi * 16 + gid;
                const int w0 = ks * 8 + tig;
                ah[mi][0] = ah_s[r * AWP + w0];
                ah[mi][1] = ah_s[(r + 8) * AWP + w0];
                ah[mi][2] = ah_s[r * AWP + w0 + 4];
                ah[mi][3] = ah_s[(r + 8) * AWP + w0 + 4];
                al[mi][0] = al_s[r * AWP + w0];
                al[mi][1] = al_s[(r + 8) * AWP + w0];
                al[mi][2] = al_s[r * AWP + w0 + 4];
                al[mi][3] = al_s[(r + 8) * AWP + w0 + 4];
            }
            uint32_t bh[8][2], bl[8][2];
#pragma unroll
            for (int ni = 0; ni < 8; ni++) {
                const int c = wn + ni * 8 + gid;
                const int w0 = ks * 8 + tig;
                bh[ni][0] = bh_s[c * AWP + w0];
                bh[ni][1] = bh_s[c * AWP + w0 + 4];
                bl[ni][0] = bl_s[c * AWP + w0];
                bl[ni][1] = bl_s[c * AWP + w0 + 4];
            }
#pragma unroll
            for (int mi = 0; mi < 2; mi++)
#pragma unroll
                for (int ni = 0; ni < 8; ni++) {
                    MMA_BF16(acc[mi * 8 + ni], ah[mi], bh[ni]);
                    MMA_BF16(acc[mi * 8 + ni], ah[mi], bl[ni]);
                    MMA_BF16(acc[mi * 8 + ni], al[mi], bh[ni]);
                }
        }
        __syncthreads();
    }

#pragma unroll
    for (int mi = 0; mi < 2; mi++) {
#pragma unroll
        for (int ni = 0; ni < 8; ni++) {
            const int row = bm + wm + mi * 16 + gid;
            const int col = bn + wn + ni * 8 + tig * 2;
            const float b0 = bias[col];
            const float b1 = bias[col + 1];
            const float* c = acc[mi * 8 + ni];
#pragma unroll
            for (int half = 0; half < 2; half++) {
                const int m = row + half * 8;
                float v0 = c[half * 2 + 0] + b0;
                float v1 = c[half * 2 + 1] + b1;
                if (MODE == 0) {
                    float* dst = outf + (size_t)m * DIM + col;
                    dst[0] = v0;
                    dst[1] = v1;
                } else if (MODE == 1 || MODE == 2) {
                    if (MODE == 1) { v0 *= 0.125f; v1 *= 0.125f; }
                    const int b  = m / S_LEN;
                    const int s  = m % S_LEN;
                    const int h  = col / DHEAD;
                    const int dw = (col % DHEAD) >> 1;
                    const size_t idx = ((size_t)(b * NH + h) * S_LEN + s) * 32 + dw;
                    uint32_t hw, lw;
                    split2(v0, v1, hw, lw);
                    outh[idx] = hw;
                    outl[idx] = lw;
                } else {  // MODE 3: V transposed
                    const int b  = m / S_LEN;
                    const int s  = m % S_LEN;
                    const int h  = col / DHEAD;
                    const int dh = col % DHEAD;
                    const int n  = b * NH + h;
                    __nv_bfloat16* VH = (__nv_bfloat16*)outh;
                    __nv_bfloat16* VL = (__nv_bfloat16*)outl;
                    __nv_bfloat16 h0 = __float2bfloat16(v0);
                    __nv_bfloat16 h1 = __float2bfloat16(v1);
                    __nv_bfloat16 l0 = __float2bfloat16(v0 - __bfloat162float(h0));
                    __nv_bfloat16 l1 = __float2bfloat16(v1 - __bfloat162float(h1));
                    const size_t base = ((size_t)n * DHEAD + dh) * S_LEN + s;
                    VH[base] = h0; VL[base] = l0;
                    VH[base + S_LEN] = h1; VL[base + S_LEN] = l1;
                }
            }
        }
    }
}

// ---------------------------------------------------------------------------
// Flash attention, all-bf16 3x emulation, q-tile = 128 rows (8 warps),
// double-buffered K/V staging (2-deep cp.async pipeline).
// SMEM: 2 KV buffers (Kh,Kl,Vh,Vl @ 64x36 words) + Ph,Pl (128x36) = 110592 B.
// ---------------------------------------------------------------------------
#define KWP 36
#define KVW (64 * KWP)       // words per plane per tile (2304)
#define KVBUF (4 * KVW)      // 4 planes per buffer (9216)
#define PW (128 * KWP)       // P plane words (4608)
#define FSMW (2 * KVBUF + 2 * PW)   // 27648 words = 110592 B

__global__ void __launch_bounds__(256, 2) flash_bf16()
{
    extern __shared__ uint32_t fsw[];
    uint32_t* Phs = fsw + 2 * KVBUF;
    uint32_t* Pls = Phs + PW;

    const int qt   = (int)gridDim.x - 1 - (int)blockIdx.x;  // 0..15, heavy first
    const int n    = blockIdx.y;
    const int tid  = threadIdx.x;
    const int lane = tid & 31;
    const int w    = tid >> 5;          // 0..7
    const int gid  = lane >> 2;
    const int tig  = lane & 3;

    const int r0 = w * 16 + gid;        // 0..127
    const int r1 = r0 + 8;

    // Q fragments (pre-scaled, pre-split words)
    const uint32_t* Qhg = g_Qh + ((size_t)n * S_LEN + qt * 128) * 32;
    const uint32_t* Qlg = g_Ql + ((size_t)n * S_LEN + qt * 128) * 32;
    uint32_t qh[4][4], ql[4][4];
#pragma unroll
    for (int ks = 0; ks < 4; ks++) {
        const int w0 = ks * 8 + tig;
        qh[ks][0] = Qhg[r0 * 32 + w0];
        qh[ks][1] = Qhg[r1 * 32 + w0];
        qh[ks][2] = Qhg[r0 * 32 + w0 + 4];
        qh[ks][3] = Qhg[r1 * 32 + w0 + 4];
        ql[ks][0] = Qlg[r0 * 32 + w0];
        ql[ks][1] = Qlg[r1 * 32 + w0];
        ql[ks][2] = Qlg[r0 * 32 + w0 + 4];
        ql[ks][3] = Qlg[r1 * 32 + w0 + 4];
    }

    float m0 = -1.0e30f, m1 = -1.0e30f, l0 = 0.0f, l1 = 0.0f;
    float o[8][4];
#pragma unroll
    for (int i = 0; i < 8; i++)
#pragma unroll
        for (int j = 0; j < 4; j++) o[i][j] = 0.0f;

    // staging: 256 threads, 64 rows x 32 words; 4 threads/row x 8 words
    const int srow = tid >> 2;          // 0..63
    const int soff = (tid & 3) * 8;     // 0,8,16,24 words

    const uint32_t* Khg = g_Kh  + (size_t)n * S_LEN * 32;
    const uint32_t* Klg = g_Kl  + (size_t)n * S_LEN * 32;
    const uint32_t* Vhg = g_Vth + (size_t)n * DHEAD * (S_LEN / 2);
    const uint32_t* Vlg = g_Vtl + (size_t)n * DHEAD * (S_LEN / 2);

    auto stage = [&](int buf, int kt) {
        const uint32_t* sKh = Khg + (size_t)(kt * 64 + srow) * 32 + soff;
        const uint32_t* sKl = Klg + (size_t)(kt * 64 + srow) * 32 + soff;
        const uint32_t* sVh = Vhg + (size_t)srow * (S_LEN / 2) + kt * 32 + soff;
        const uint32_t* sVl = Vlg + (size_t)srow * (S_LEN / 2) + kt * 32 + soff;
        const uint32_t base = cvta_smem(fsw + buf * KVBUF + srow * KWP + soff);
        cp_async16(base,                    sKh);
        cp_async16(base + 16,               sKh + 4);
        cp_async16(base + KVW * 4,          sKl);
        cp_async16(base + KVW * 4 + 16,     sKl + 4);
        cp_async16(base + 2 * KVW * 4,      sVh);
        cp_async16(base + 2 * KVW * 4 + 16, sVh + 4);
        cp_async16(base + 3 * KVW * 4,      sVl);
        cp_async16(base + 3 * KVW * 4 + 16, sVl + 4);
        cp_commit();
    };

    const int ktmax = 2 * qt + 1;
    stage(0, 0);

    int buf = 0;
    for (int kt = 0; kt <= ktmax; kt++, buf ^= 1) {
        __syncthreads();   // all warps done reading buf^1 (kt-1) before restage
        if (kt < ktmax) {
            stage(buf ^ 1, kt + 1);
            asm volatile("cp.async.wait_group 1;");
        } else {
            asm volatile("cp.async.wait_group 0;");
        }
        __syncthreads();

        const uint32_t* Khs = fsw + buf * KVBUF;
        const uint32_t* Kls = Khs + KVW;
        const uint32_t* Vhs = Khs + 2 * KVW;
        const uint32_t* Vls = Khs + 3 * KVW;

        // ---- S = Q K^T (3xBF16) ----
        float s[8][4];
#pragma unroll
        for (int i = 0; i < 8; i++)
#pragma unroll
            for (int j = 0; j < 4; j++) s[i][j] = 0.0f;

#pragma unroll
        for (int ks = 0; ks < 4; ks++) {
#pragma unroll
            for (int ni = 0; ni < 8; ni++) {
                const int kw = (ni * 8 + gid) * KWP + ks * 8 + tig;
                uint32_t bh[2] = { Khs[kw], Khs[kw + 4] };
                uint32_t bl[2] = { Kls[kw], Kls[kw + 4] };
                MMA_BF16(s[ni], qh[ks], bh);
                MMA_BF16(s[ni], qh[ks], bl);
                MMA_BF16(s[ni], ql[ks], bh);
            }
        }

        // ---- causal mask (only last two kt tiles can touch the diagonal) ----
        if (kt >= 2 * qt) {
            const int gr0 = qt * 128 + r0;
            const int gr1 = gr0 + 8;
#pragma unroll
            for (int ni = 0; ni < 8; ni++) {
                const int gc = kt * 64 + ni * 8 + tig * 2;
                if (gc > gr0)     s[ni][0] = -1.0e30f;
                if (gc + 1 > gr0) s[ni][1] = -1.0e30f;
                if (gc > gr1)     s[ni][2] = -1.0e30f;
                if (gc + 1 > gr1) s[ni][3] = -1.0e30f;
            }
        }

        // ---- online softmax ----
        float mx0 = -1.0e30f, mx1 = -1.0e30f;
#pragma unroll
        for (int ni = 0; ni < 8; ni++) {
            mx0 = fmaxf(mx0, fmaxf(s[ni][0], s[ni][1]));
            mx1 = fmaxf(mx1, fmaxf(s[ni][2], s[ni][3]));
        }
        mx0 = fmaxf(mx0, __shfl_xor_sync(0xffffffffu, mx0, 1));
        mx0 = fmaxf(mx0, __shfl_xor_sync(0xffffffffu, mx0, 2));
        mx1 = fmaxf(mx1, __shfl_xor_sync(0xffffffffu, mx1, 1));
        mx1 = fmaxf(mx1, __shfl_xor_sync(0xffffffffu, mx1, 2));

        const float mn0 = fmaxf(m0, mx0);
        const float mn1 = fmaxf(m1, mx1);
        const float a0 = __expf(m0 - mn0);
        const float a1 = __expf(m1 - mn1);
        m0 = mn0; m1 = mn1;

        float sum0 = 0.0f, sum1 = 0.0f;
#pragma unroll
        for (int ni = 0; ni < 8; ni++) {
            s[ni][0] = __expf(s[ni][0] - mn0);
            s[ni][1] = __expf(s[ni][1] - mn0);
            s[ni][2] = __expf(s[ni][2] - mn1);
            s[ni][3] = __expf(s[ni][3] - mn1);
            sum0 += s[ni][0] + s[ni][1];
            sum1 += s[ni][2] + s[ni][3];
        }
        sum0 += __shfl_xor_sync(0xffffffffu, sum0, 1);
        sum0 += __shfl_xor_sync(0xffffffffu, sum0, 2);
        sum1 += __shfl_xor_sync(0xffffffffu, sum1, 1);
        sum1 += __shfl_xor_sync(0xffffffffu, sum1, 2);
        l0 = l0 * a0 + sum0;
        l1 = l1 * a1 + sum1;

#pragma unroll
        for (int ni = 0; ni < 8; ni++) {
            o[ni][0] *= a0; o[ni][1] *= a0;
            o[ni][2] *= a1; o[ni][3] *= a1;
        }

        // ---- stage P as bf16 hi/lo words (same-warp producer/consumer) ----
#pragma unroll
        for (int ni = 0; ni < 8; ni++) {
            const int wi0 = r0 * KWP + ni * 4 + tig;
            const int wi1 = r1 * KWP + ni * 4 + tig;
            uint32_t hw, lw;
            split2(s[ni][0], s[ni][1], hw, lw);
            Phs[wi0] = hw; Pls[wi0] = lw;
            split2(s[ni][2], s[ni][3], hw, lw);
            Phs[wi1] = hw; Pls[wi1] = lw;
        }
        __syncwarp();

        // ---- O += P V (3xBF16) ----
#pragma unroll
        for (int ks = 0; ks < 4; ks++) {
            const int w0 = ks * 8 + tig;
            uint32_t ph[4] = { Phs[r0 * KWP + w0], Phs[r1 * KWP + w0],
                               Phs[r0 * KWP + w0 + 4], Phs[r1 * KWP + w0 + 4] };
            uint32_t pl[4] = { Pls[r0 * KWP + w0], Pls[r1 * KWP + w0],
                               Pls[r0 * KWP + w0 + 4], Pls[r1 * KWP + w0 + 4] };
#pragma unroll
            for (int ni = 0; ni < 8; ni++) {
                const int vw = (ni * 8 + gid) * KWP + ks * 8 + tig;
                uint32_t bh[2] = { Vhs[vw], Vhs[vw + 4] };
                uint32_t bl[2] = { Vls[vw], Vls[vw + 4] };
                MMA_BF16(o[ni], ph, bh);
                MMA_BF16(o[ni], ph, bl);
                MMA_BF16(o[ni], pl, bh);
            }
        }
    }

    // ---- epilogue: normalize, split, store AO word planes (concat-head) ----
    const float inv0 = 1.0f / l0;
    const float inv1 = 1.0f / l1;
    const int b = n >> 4;
    const int h = n & 15;
    const int rowg0 = b * S_LEN + qt * 128 + r0;
    const int rowg1 = rowg0 + 8;
#pragma unroll
    for (int ni = 0; ni < 8; ni++) {
        const int cw = h * 32 + ni * 4 + tig;
        uint32_t hw, lw;
        split2(o[ni][0] * inv0, o[ni][1] * inv0, hw, lw);
        g_AOh[(size_t)rowg0 * 512 + cw] = hw;
        g_AOl[(size_t)rowg0 * 512 + cw] = lw;
        split2(o[ni][2] * inv1, o[ni][3] * inv1, hw, lw);
        g_AOh[(size_t)rowg1 * 512 + cw] = hw;
        g_AOl[(size_t)rowg1 * 512 + cw] = lw;
    }
}

// ---------------------------------------------------------------------------
// kernel_launch: x, mask, Wq, bq, Wk, bk, Wv, bv, Wo, bo
// ---------------------------------------------------------------------------
extern "C" void kernel_launch(void* const* d_in, const int* in_sizes, int n_in,
                              void* d_out, int out_size)
{
    const float* x  = (const float*)d_in[0];
    const float* Wq = (const float*)d_in[2];
    const float* bq = (const float*)d_in[3];
    const float* Wk = (const float*)d_in[4];
    const float* bk = (const float*)d_in[5];
    const float* Wv = (const float*)d_in[6];
    const float* bv = (const float*)d_in[7];
    const float* Wo = (const float*)d_in[8];
    const float* bo = (const float*)d_in[9];
    float* out = (float*)d_out;

    uint32_t *xh, *xl, *Wqh, *Wql, *Wkh, *Wkl, *Wvh, *Wvl, *Woh, *Wol;
    uint32_t *Qh, *Ql, *Kh, *Kl, *Vth, *Vtl, *AOh, *AOl;
    cudaGetSymbolAddress((void**)&xh,  g_xh);  cudaGetSymbolAddress((void**)&xl,  g_xl);
    cudaGetSymbolAddress((void**)&Wqh, g_Wqh); cudaGetSymbolAddress((void**)&Wql, g_Wql);
    cudaGetSymbolAddress((void**)&Wkh, g_Wkh); cudaGetSymbolAddress((void**)&Wkl, g_Wkl);
    cudaGetSymbolAddress((void**)&Wvh, g_Wvh); cudaGetSymbolAddress((void**)&Wvl, g_Wvl);
    cudaGetSymbolAddress((void**)&Woh, g_Woh); cudaGetSymbolAddress((void**)&Wol, g_Wol);
    cudaGetSymbolAddress((void**)&Qh,  g_Qh);  cudaGetSymbolAddress((void**)&Ql,  g_Ql);
    cudaGetSymbolAddress((void**)&Kh,  g_Kh);  cudaGetSymbolAddress((void**)&Kl,  g_Kl);
    cudaGetSymbolAddress((void**)&Vth, g_Vth); cudaGetSymbolAddress((void**)&Vtl, g_Vtl);
    cudaGetSymbolAddress((void**)&AOh, g_AOh); cudaGetSymbolAddress((void**)&AOl, g_AOl);

    // Prepass splits
    split_bf16<<<(M_ROWS * DIM / 4 + 255) / 256, 256>>>(x,  xh,  xl,  M_ROWS * DIM / 4);
    split_bf16<<<(DIM * DIM / 4 + 255) / 256, 256>>>(Wq, Wqh, Wql, DIM * DIM / 4);
    split_bf16<<<(DIM * DIM / 4 + 255) / 256, 256>>>(Wk, Wkh, Wkl, DIM * DIM / 4);
    split_bf16<<<(DIM * DIM / 4 + 255) / 256, 256>>>(Wv, Wvh, Wvl, DIM * DIM / 4);
    split_bf16<<<(DIM * DIM / 4 + 255) / 256, 256>>>(Wo, Woh, Wol, DIM * DIM / 4);

    const int gsmem = 8 * GTILEW * (int)sizeof(uint32_t);  // 81920
    cudaFuncSetAttribute(gemm_bf16<0>, cudaFuncAttributeMaxDynamicSharedMemorySize, gsmem);
    cudaFuncSetAttribute(gemm_bf16<1>, cudaFuncAttributeMaxDynamicSharedMemorySize, gsmem);
    cudaFuncSetAttribute(gemm_bf16<2>, cudaFuncAttributeMaxDynamicSharedMemorySize, gsmem);
    cudaFuncSetAttribute(gemm_bf16<3>, cudaFuncAttributeMaxDynamicSharedMemorySize, gsmem);

    const dim3 ggrid(DIM / 128, M_ROWS / 128);  // (8, 32)
    gemm_bf16<1><<<ggrid, 256, gsmem>>>(xh, xl, Wqh, Wql, bq, nullptr, Qh, Ql);
    gemm_bf16<2><<<ggrid, 256, gsmem>>>(xh, xl, Wkh, Wkl, bk, nullptr, Kh, Kl);
    gemm_bf16<3><<<ggrid, 256, gsmem>>>(xh, xl, Wvh, Wvl, bv, nullptr, Vth, Vtl);

    const int fsmem = FSMW * (int)sizeof(uint32_t);  // 110592
    cudaFuncSetAttribute(flash_bf16, cudaFuncAttributeMaxDynamicSharedMemorySize, fsmem);
    flash_bf16<<<dim3(S_LEN / 128, BATCH * NH), 256, fsmem>>>();

    gemm_bf16<0><<<ggrid, 256, gsmem>>>(AOh, AOl, Woh, Wol, bo, out, nullptr, nullptr);
}

// round 8
// speedup vs baseline: 3.6697x; 1.0283x over previous
#include <cuda_runtime.h>
#include <cuda_bf16.h>
#include <math.h>
#include <stdint.h>

#define S_LEN 2048
#define DIM   1024
#define NH    16
#define DHEAD 64
#define BATCH 2
#define M_ROWS (BATCH * S_LEN)   // 4096
#define NW     (M_ROWS * DIM / 2)
#define WW     (DIM * DIM / 2)

// bf16x2-packed hi/lo planes (low half = even k)
__device__ uint32_t g_xh[NW],  g_xl[NW];
__device__ uint32_t g_Wqh[WW], g_Wql[WW];
__device__ uint32_t g_Wkh[WW], g_Wkl[WW];
__device__ uint32_t g_Wvh[WW], g_Wvl[WW];
__device__ uint32_t g_Woh[WW], g_Wol[WW];
__device__ uint32_t g_Qh[NW], g_Ql[NW];   // Q pre-scaled by 0.125*log2(e)
__device__ uint32_t g_Kh[NW], g_Kl[NW];
__device__ uint32_t g_Vth[NW], g_Vtl[NW]; // V transposed [n][dh][s/2]
__device__ uint32_t g_AOh[NW], g_AOl[NW];

// ---------------------------------------------------------------------------
// Helpers
// ---------------------------------------------------------------------------
__device__ __forceinline__ uint32_t cvta_smem(const void* p) {
    return (uint32_t)__cvta_generic_to_shared(p);
}
__device__ __forceinline__ void cp_async16(uint32_t dst, const void* src) {
    asm volatile("cp.async.cg.shared.global [%0], [%1], 16;" :: "r"(dst), "l"(src));
}
__device__ __forceinline__ void cp_commit() {
    asm volatile("cp.async.commit_group;");
}
__device__ __forceinline__ uint32_t packbf(float e0, float e1) {
    uint32_t r;
    asm("cvt.rn.bf16x2.f32 %0, %1, %2;" : "=r"(r) : "f"(e1), "f"(e0));
    return r;
}
__device__ __forceinline__ void split2(float e0, float e1, uint32_t& h, uint32_t& l) {
    h = packbf(e0, e1);
    float h0 = __uint_as_float(h << 16);
    float h1 = __uint_as_float(h & 0xFFFF0000u);
    l = packbf(e0 - h0, e1 - h1);
}
__device__ __forceinline__ float ex2f(float x) {
    float r;
    asm("ex2.approx.f32 %0, %1;" : "=f"(r) : "f"(x));
    return r;
}

#define MMA_BF16(c, a, b)                                                     \
    asm volatile(                                                             \
        "mma.sync.aligned.m16n8k16.row.col.f32.bf16.bf16.f32 "                \
        "{%0,%1,%2,%3}, {%4,%5,%6,%7}, {%8,%9}, {%0,%1,%2,%3};"               \
        : "+f"((c)[0]), "+f"((c)[1]), "+f"((c)[2]), "+f"((c)[3])              \
        : "r"((a)[0]), "r"((a)[1]), "r"((a)[2]), "r"((a)[3]),                 \
          "r"((b)[0]), "r"((b)[1]))

// ---------------------------------------------------------------------------
// Prepass split
// ---------------------------------------------------------------------------
__global__ void __launch_bounds__(256) split_bf16(
    const float* __restrict__ in, uint32_t* __restrict__ oh,
    uint32_t* __restrict__ ol, int n4)
{
    const int i = blockIdx.x * blockDim.x + threadIdx.x;
    if (i >= n4) return;
    float4 v = ((const float4*)in)[i];
    uint32_t h0, l0, h1, l1;
    split2(v.x, v.y, h0, l0);
    split2(v.z, v.w, h1, l1);
    ((uint2*)oh)[i] = make_uint2(h0, h1);
    ((uint2*)ol)[i] = make_uint2(l0, l1);
}

// ---------------------------------------------------------------------------
// 3xBF16 GEMM on packed planes (structure from round 5/6).
// MODE 0: fp32 out; 1: Q planes (x 0.125*log2e); 2: K planes; 3: V transposed.
// ---------------------------------------------------------------------------
#define BKW 16
#define AWP 20
#define GTILEW (128 * AWP)
#define QSCALE (0.125f * 1.4426950408889634f)

template <int MODE>
__global__ void __launch_bounds__(256, 2)
gemm_bf16(const uint32_t* __restrict__ Ahg, const uint32_t* __restrict__ Alg,
          const uint32_t* __restrict__ Bhg, const uint32_t* __restrict__ Blg,
          const float* __restrict__ bias,
          float* __restrict__ outf,
          uint32_t* __restrict__ outh, uint32_t* __restrict__ outl)
{
    extern __shared__ uint32_t gsm[];
    uint32_t* Ahs = gsm;
    uint32_t* Als = Ahs + 2 * GTILEW;
    uint32_t* Bhs = Als + 2 * GTILEW;
    uint32_t* Bls = Bhs + 2 * GTILEW;

    const int tid  = threadIdx.x;
    const int lane = tid & 31;
    const int wid  = tid >> 5;
    const int bm = blockIdx.y * 128;
    const int bn = blockIdx.x * 128;
    const int wm = (wid >> 1) * 32;
    const int wn = (wid & 1) * 64;
    const int gid = lane >> 2;
    const int tig = lane & 3;

    const int lrow = tid >> 2;
    const int lkw  = (tid & 3) * 4;
    const uint32_t* Ah0 = Ahg + (size_t)(bm + lrow) * 512 + lkw;
    const uint32_t* Al0 = Alg + (size_t)(bm + lrow) * 512 + lkw;
    const uint32_t* Bh0 = Bhg + (size_t)(bn + lrow) * 512 + lkw;
    const uint32_t* Bl0 = Blg + (size_t)(bn + lrow) * 512 + lkw;

    float acc[16][4];
#pragma unroll
    for (int i = 0; i < 16; i++)
#pragma unroll
        for (int j = 0; j < 4; j++) acc[i][j] = 0.0f;

    auto stage = [&](int buf, int ktw) {
        const int o  = buf * GTILEW + lrow * AWP + lkw;
        const int o2 = o + 64 * AWP;
        cp_async16(cvta_smem(Ahs + o),  Ah0 + ktw);
        cp_async16(cvta_smem(Ahs + o2), Ah0 + 64 * 512 + ktw);
        cp_async16(cvta_smem(Als + o),  Al0 + ktw);
        cp_async16(cvta_smem(Als + o2), Al0 + 64 * 512 + ktw);
        cp_async16(cvta_smem(Bhs + o),  Bh0 + ktw);
        cp_async16(cvta_smem(Bhs + o2), Bh0 + 64 * 512 + ktw);
        cp_async16(cvta_smem(Bls + o),  Bl0 + ktw);
        cp_async16(cvta_smem(Bls + o2), Bl0 + 64 * 512 + ktw);
        cp_commit();
    };

    stage(0, 0);

    int buf = 0;
    for (int ktw = 0; ktw < 512; ktw += BKW, buf ^= 1) {
        if (ktw + BKW < 512) {
            stage(buf ^ 1, ktw + BKW);
            asm volatile("cp.async.wait_group 1;");
        } else {
            asm volatile("cp.async.wait_group 0;");
        }
        __syncthreads();

        const uint32_t* ah_s = Ahs + buf * GTILEW;
        const uint32_t* al_s = Als + buf * GTILEW;
        const uint32_t* bh_s = Bhs + buf * GTILEW;
        const uint32_t* bl_s = Bls + buf * GTILEW;

#pragma unroll
        for (int ks = 0; ks < 2; ks++) {
            uint32_t ah[2][4], al[2][4];
#pragma unroll
            for (int mi = 0; mi < 2; mi++) {
                const int r = wm + mi * 16 + gid;
                const int w0 = ks * 8 + tig;
                ah[mi][0] = ah_s[r * AWP + w0];
                ah[mi][1] = ah_s[(r + 8) * AWP + w0];
                ah[mi][2] = ah_s[r * AWP + w0 + 4];
                ah[mi][3] = ah_s[(r + 8) * AWP + w0 + 4];
                al[mi][0] = al_s[r * AWP + w0];
                al[mi][1] = al_s[(r + 8) * AWP + w0];
                al[mi][2] = al_s[r * AWP + w0 + 4];
                al[mi][3] = al_s[(r + 8) * AWP + w0 + 4];
            }
            uint32_t bh[8][2], bl[8][2];
#pragma unroll
            for (int ni = 0; ni < 8; ni++) {
                const int c = wn + ni * 8 + gid;
                const int w0 = ks * 8 + tig;
                bh[ni][0] = bh_s[c * AWP + w0];
                bh[ni][1] = bh_s[c * AWP + w0 + 4];
                bl[ni][0] = bl_s[c * AWP + w0];
                bl[ni][1] = bl_s[c * AWP + w0 + 4];
            }
#pragma unroll
            for (int mi = 0; mi < 2; mi++)
#pragma unroll
                for (int ni = 0; ni < 8; ni++) {
                    MMA_BF16(acc[mi * 8 + ni], ah[mi], bh[ni]);
                    MMA_BF16(acc[mi * 8 + ni], ah[mi], bl[ni]);
                    MMA_BF16(acc[mi * 8 + ni], al[mi], bh[ni]);
                }
        }
        __syncthreads();
    }

#pragma unroll
    for (int mi = 0; mi < 2; mi++) {
#pragma unroll
        for (int ni = 0; ni < 8; ni++) {
            const int row = bm + wm + mi * 16 + gid;
            const int col = bn + wn + ni * 8 + tig * 2;
            const float b0 = bias[col];
            const float b1 = bias[col + 1];
            const float* c = acc[mi * 8 + ni];
#pragma unroll
            for (int half = 0; half < 2; half++) {
                const int m = row + half * 8;
                float v0 = c[half * 2 + 0] + b0;
                float v1 = c[half * 2 + 1] + b1;
                if (MODE == 0) {
                    float* dst = outf + (size_t)m * DIM + col;
                    dst[0] = v0;
                    dst[1] = v1;
                } else if (MODE == 1 || MODE == 2) {
                    if (MODE == 1) { v0 *= QSCALE; v1 *= QSCALE; }
                    const int b  = m / S_LEN;
                    const int s  = m % S_LEN;
                    const int h  = col / DHEAD;
                    const int dw = (col % DHEAD) >> 1;
                    const size_t idx = ((size_t)(b * NH + h) * S_LEN + s) * 32 + dw;
                    uint32_t hw, lw;
                    split2(v0, v1, hw, lw);
                    outh[idx] = hw;
                    outl[idx] = lw;
                } else {  // MODE 3: V transposed [n][dh][s]
                    const int b  = m / S_LEN;
                    const int s  = m % S_LEN;
                    const int h  = col / DHEAD;
                    const int dh = col % DHEAD;
                    const int n  = b * NH + h;
                    __nv_bfloat16* VH = (__nv_bfloat16*)outh;
                    __nv_bfloat16* VL = (__nv_bfloat16*)outl;
                    __nv_bfloat16 h0 = __float2bfloat16(v0);
                    __nv_bfloat16 h1 = __float2bfloat16(v1);
                    __nv_bfloat16 l0 = __float2bfloat16(v0 - __bfloat162float(h0));
                    __nv_bfloat16 l1 = __float2bfloat16(v1 - __bfloat162float(h1));
                    const size_t base = ((size_t)n * DHEAD + dh) * S_LEN + s;
                    VH[base] = h0; VL[base] = l0;
                    VH[base + S_LEN] = h1; VL[base + S_LEN] = l1;
                }
            }
        }
    }
}

// ---------------------------------------------------------------------------
// Flash attention, 3xBF16, q-tile 128 (8 warps), double-buffered K/V,
// P kept entirely in registers (C-frag == A-frag layout trick), base-2 softmax.
// SMEM: 2 KV buffers x 4 planes x 64 x 36 words = 73728 B.
// ---------------------------------------------------------------------------
#define KWP 36
#define KVW (64 * KWP)
#define KVBUF (4 * KVW)
#define FSMW (2 * KVBUF)

__global__ void __launch_bounds__(256, 2) flash_bf16()
{
    extern __shared__ uint32_t fsw[];

    const int qt   = (int)gridDim.x - 1 - (int)blockIdx.x;
    const int n    = blockIdx.y;
    const int tid  = threadIdx.x;
    const int lane = tid & 31;
    const int w    = tid >> 5;
    const int gid  = lane >> 2;
    const int tig  = lane & 3;

    const int r0 = w * 16 + gid;
    const int r1 = r0 + 8;

    const uint32_t* Qhg = g_Qh + ((size_t)n * S_LEN + qt * 128) * 32;
    const uint32_t* Qlg = g_Ql + ((size_t)n * S_LEN + qt * 128) * 32;
    uint32_t qh[4][4], ql[4][4];
#pragma unroll
    for (int ks = 0; ks < 4; ks++) {
        const int w0 = ks * 8 + tig;
        qh[ks][0] = Qhg[r0 * 32 + w0];
        qh[ks][1] = Qhg[r1 * 32 + w0];
        qh[ks][2] = Qhg[r0 * 32 + w0 + 4];
        qh[ks][3] = Qhg[r1 * 32 + w0 + 4];
        ql[ks][0] = Qlg[r0 * 32 + w0];
        ql[ks][1] = Qlg[r1 * 32 + w0];
        ql[ks][2] = Qlg[r0 * 32 + w0 + 4];
        ql[ks][3] = Qlg[r1 * 32 + w0 + 4];
    }

    float m0 = -1.0e30f, m1 = -1.0e30f, l0 = 0.0f, l1 = 0.0f;
    float o[8][4];
#pragma unroll
    for (int i = 0; i < 8; i++)
#pragma unroll
        for (int j = 0; j < 4; j++) o[i][j] = 0.0f;

    const int srow = tid >> 2;
    const int soff = (tid & 3) * 8;

    const uint32_t* Khg = g_Kh  + (size_t)n * S_LEN * 32;
    const uint32_t* Klg = g_Kl  + (size_t)n * S_LEN * 32;
    const uint32_t* Vhg = g_Vth + (size_t)n * DHEAD * (S_LEN / 2);
    const uint32_t* Vlg = g_Vtl + (size_t)n * DHEAD * (S_LEN / 2);

    auto stage = [&](int buf, int kt) {
        const uint32_t* sKh = Khg + (size_t)(kt * 64 + srow) * 32 + soff;
        const uint32_t* sKl = Klg + (size_t)(kt * 64 + srow) * 32 + soff;
        const uint32_t* sVh = Vhg + (size_t)srow * (S_LEN / 2) + kt * 32 + soff;
        const uint32_t* sVl = Vlg + (size_t)srow * (S_LEN / 2) + kt * 32 + soff;
        const uint32_t base = cvta_smem(fsw + buf * KVBUF + srow * KWP + soff);
        cp_async16(base,                    sKh);
        cp_async16(base + 16,               sKh + 4);
        cp_async16(base + KVW * 4,          sKl);
        cp_async16(base + KVW * 4 + 16,     sKl + 4);
        cp_async16(base + 2 * KVW * 4,      sVh);
        cp_async16(base + 2 * KVW * 4 + 16, sVh + 4);
        cp_async16(base + 3 * KVW * 4,      sVl);
        cp_async16(base + 3 * KVW * 4 + 16, sVl + 4);
        cp_commit();
    };

    const int ktmax = 2 * qt + 1;
    stage(0, 0);

    int buf = 0;
    for (int kt = 0; kt <= ktmax; kt++, buf ^= 1) {
        __syncthreads();
        if (kt < ktmax) {
            stage(buf ^ 1, kt + 1);
            asm volatile("cp.async.wait_group 1;");
        } else {
            asm volatile("cp.async.wait_group 0;");
        }
        __syncthreads();

        const uint32_t* Khs = fsw + buf * KVBUF;
        const uint32_t* Kls = Khs + KVW;
        const uint32_t* Vhs = Khs + 2 * KVW;
        const uint32_t* Vls = Khs + 3 * KVW;

        // ---- S = Q K^T (3xBF16), result in log2 units ----
        float s[8][4];
#pragma unroll
        for (int i = 0; i < 8; i++)
#pragma unroll
            for (int j = 0; j < 4; j++) s[i][j] = 0.0f;

#pragma unroll
        for (int ks = 0; ks < 4; ks++) {
#pragma unroll
            for (int ni = 0; ni < 8; ni++) {
                const int kw = (ni * 8 + gid) * KWP + ks * 8 + tig;
                uint32_t bh[2] = { Khs[kw], Khs[kw + 4] };
                uint32_t bl[2] = { Kls[kw], Kls[kw + 4] };
                MMA_BF16(s[ni], qh[ks], bh);
                MMA_BF16(s[ni], qh[ks], bl);
                MMA_BF16(s[ni], ql[ks], bh);
            }
        }

        // ---- causal mask (only last two kt tiles can touch the diagonal) ----
        if (kt >= 2 * qt) {
            const int gr0 = qt * 128 + r0;
            const int gr1 = gr0 + 8;
#pragma unroll
            for (int ni = 0; ni < 8; ni++) {
                const int gc = kt * 64 + ni * 8 + tig * 2;
                if (gc > gr0)     s[ni][0] = -1.0e30f;
                if (gc + 1 > gr0) s[ni][1] = -1.0e30f;
                if (gc > gr1)     s[ni][2] = -1.0e30f;
                if (gc + 1 > gr1) s[ni][3] = -1.0e30f;
            }
        }

        // ---- online softmax (base 2) ----
        float mx0 = -1.0e30f, mx1 = -1.0e30f;
#pragma unroll
        for (int ni = 0; ni < 8; ni++) {
            mx0 = fmaxf(mx0, fmaxf(s[ni][0], s[ni][1]));
            mx1 = fmaxf(mx1, fmaxf(s[ni][2], s[ni][3]));
        }
        mx0 = fmaxf(mx0, __shfl_xor_sync(0xffffffffu, mx0, 1));
        mx0 = fmaxf(mx0, __shfl_xor_sync(0xffffffffu, mx0, 2));
        mx1 = fmaxf(mx1, __shfl_xor_sync(0xffffffffu, mx1, 1));
        mx1 = fmaxf(mx1, __shfl_xor_sync(0xffffffffu, mx1, 2));

        const float mn0 = fmaxf(m0, mx0);
        const float mn1 = fmaxf(m1, mx1);
        const float a0 = ex2f(m0 - mn0);
        const float a1 = ex2f(m1 - mn1);
        m0 = mn0; m1 = mn1;

        float sum0 = 0.0f, sum1 = 0.0f;
#pragma unroll
        for (int ni = 0; ni < 8; ni++) {
            s[ni][0] = ex2f(s[ni][0] - mn0);
            s[ni][1] = ex2f(s[ni][1] - mn0);
            s[ni][2] = ex2f(s[ni][2] - mn1);
            s[ni][3] = ex2f(s[ni][3] - mn1);
            sum0 += s[ni][0] + s[ni][1];
            sum1 += s[ni][2] + s[ni][3];
        }
        sum0 += __shfl_xor_sync(0xffffffffu, sum0, 1);
        sum0 += __shfl_xor_sync(0xffffffffu, sum0, 2);
        sum1 += __shfl_xor_sync(0xffffffffu, sum1, 1);
        sum1 += __shfl_xor_sync(0xffffffffu, sum1, 2);
        l0 = l0 * a0 + sum0;
        l1 = l1 * a1 + sum1;

#pragma unroll
        for (int ni = 0; ni < 8; ni++) {
            o[ni][0] *= a0; o[ni][1] *= a0;
            o[ni][2] *= a1; o[ni][3] *= a1;
        }

        // ---- O += P V : P stays in registers (C-frag == A-frag layout) ----
#pragma unroll
        for (int j = 0; j < 4; j++) {
            uint32_t ph[4], pl[4];
            split2(s[2 * j][0],     s[2 * j][1],     ph[0], pl[0]);
            split2(s[2 * j][2],     s[2 * j][3],     ph[1], pl[1]);
            split2(s[2 * j + 1][0], s[2 * j + 1][1], ph[2], pl[2]);
            split2(s[2 * j + 1][2], s[2 * j + 1][3], ph[3], pl[3]);
#pragma unroll
            for (int ni = 0; ni < 8; ni++) {
                const int vw = (ni * 8 + gid) * KWP + j * 8 + tig;
                uint32_t bh[2] = { Vhs[vw], Vhs[vw + 4] };
                uint32_t bl[2] = { Vls[vw], Vls[vw + 4] };
                MMA_BF16(o[ni], ph, bh);
                MMA_BF16(o[ni], ph, bl);
                MMA_BF16(o[ni], pl, bh);
            }
        }
    }

    // ---- epilogue: normalize, split, store AO word planes (concat-head) ----
    const float inv0 = 1.0f / l0;
    const float inv1 = 1.0f / l1;
    const int b = n >> 4;
    const int h = n & 15;
    const int rowg0 = b * S_LEN + qt * 128 + r0;
    const int rowg1 = rowg0 + 8;
#pragma unroll
    for (int ni = 0; ni < 8; ni++) {
        const int cw = h * 32 + ni * 4 + tig;
        uint32_t hw, lw;
        split2(o[ni][0] * inv0, o[ni][1] * inv0, hw, lw);
        g_AOh[(size_t)rowg0 * 512 + cw] = hw;
        g_AOl[(size_t)rowg0 * 512 + cw] = lw;
        split2(o[ni][2] * inv1, o[ni][3] * inv1, hw, lw);
        g_AOh[(size_t)rowg1 * 512 + cw] = hw;
        g_AOl[(size_t)rowg1 * 512 + cw] = lw;
    }
}

// ---------------------------------------------------------------------------
// kernel_launch: x, mask, Wq, bq, Wk, bk, Wv, bv, Wo, bo
// ---------------------------------------------------------------------------
extern "C" void kernel_launch(void* const* d_in, const int* in_sizes, int n_in,
                              void* d_out, int out_size)
{
    const float* x  = (const float*)d_in[0];
    const float* Wq = (const float*)d_in[2];
    const float* bq = (const float*)d_in[3];
    const float* Wk = (const float*)d_in[4];
    const float* bk = (const float*)d_in[5];
    const float* Wv = (const float*)d_in[6];
    const float* bv = (const float*)d_in[7];
    const float* Wo = (const float*)d_in[8];
    const float* bo = (const float*)d_in[9];
    float* out = (float*)d_out;

    uint32_t *xh, *xl, *Wqh, *Wql, *Wkh, *Wkl, *Wvh, *Wvl, *Woh, *Wol;
    uint32_t *Qh, *Ql, *Kh, *Kl, *Vth, *Vtl, *AOh, *AOl;
    cudaGetSymbolAddress((void**)&xh,  g_xh);  cudaGetSymbolAddress((void**)&xl,  g_xl);
    cudaGetSymbolAddress((void**)&Wqh, g_Wqh); cudaGetSymbolAddress((void**)&Wql, g_Wql);
    cudaGetSymbolAddress((void**)&Wkh, g_Wkh); cudaGetSymbolAddress((void**)&Wkl, g_Wkl);
    cudaGetSymbolAddress((void**)&Wvh, g_Wvh); cudaGetSymbolAddress((void**)&Wvl, g_Wvl);
    cudaGetSymbolAddress((void**)&Woh, g_Woh); cudaGetSymbolAddress((void**)&Wol, g_Wol);
    cudaGetSymbolAddress((void**)&Qh,  g_Qh);  cudaGetSymbolAddress((void**)&Ql,  g_Ql);
    cudaGetSymbolAddress((void**)&Kh,  g_Kh);  cudaGetSymbolAddress((void**)&Kl,  g_Kl);
    cudaGetSymbolAddress((void**)&Vth, g_Vth); cudaGetSymbolAddress((void**)&Vtl, g_Vtl);
    cudaGetSymbolAddress((void**)&AOh, g_AOh); cudaGetSymbolAddress((void**)&AOl, g_AOl);

    split_bf16<<<(M_ROWS * DIM / 4 + 255) / 256, 256>>>(x,  xh,  xl,  M_ROWS * DIM / 4);
    split_bf16<<<(DIM * DIM / 4 + 255) / 256, 256>>>(Wq, Wqh, Wql, DIM * DIM / 4);
    split_bf16<<<(DIM * DIM / 4 + 255) / 256, 256>>>(Wk, Wkh, Wkl, DIM * DIM / 4);
    split_bf16<<<(DIM * DIM / 4 + 255) / 256, 256>>>(Wv, Wvh, Wvl, DIM * DIM / 4);
    split_bf16<<<(DIM * DIM / 4 + 255) / 256, 256>>>(Wo, Woh, Wol, DIM * DIM / 4);

    const int gsmem = 8 * GTILEW * (int)sizeof(uint32_t);  // 81920
    cudaFuncSetAttribute(gemm_bf16<0>, cudaFuncAttributeMaxDynamicSharedMemorySize, gsmem);
    cudaFuncSetAttribute(gemm_bf16<1>, cudaFuncAttributeMaxDynamicSharedMemorySize, gsmem);
    cudaFuncSetAttribute(gemm_bf16<2>, cudaFuncAttributeMaxDynamicSharedMemorySize, gsmem);
    cudaFuncSetAttribute(gemm_bf16<3>, cudaFuncAttributeMaxDynamicSharedMemorySize, gsmem);

    const dim3 ggrid(DIM / 128, M_ROWS / 128);  // (8, 32)
    gemm_bf16<1><<<ggrid, 256, gsmem>>>(xh, xl, Wqh, Wql, bq, nullptr, Qh, Ql);
    gemm_bf16<2><<<ggrid, 256, gsmem>>>(xh, xl, Wkh, Wkl, bk, nullptr, Kh, Kl);
    gemm_bf16<3><<<ggrid, 256, gsmem>>>(xh, xl, Wvh, Wvl, bv, nullptr, Vth, Vtl);

    const int fsmem = FSMW * (int)sizeof(uint32_t);  // 73728
    cudaFuncSetAttribute(flash_bf16, cudaFuncAttributeMaxDynamicSharedMemorySize, fsmem);
    flash_bf16<<<dim3(S_LEN / 128, BATCH * NH), 256, fsmem>>>();

    gemm_bf16<0><<<ggrid, 256, gsmem>>>(AOh, AOl, Woh, Wol, bo, out, nullptr, nullptr);
}